// round 1
// baseline (speedup 1.0000x reference)
#include <cuda_runtime.h>
#include <math.h>

#define Bsz  64
#define Tlen 256
#define Cdim 384
#define Hn   6
#define Dh   64
#define MTOT (Bsz*Tlen)              // 16384
#define QKV_ELEMS (Bsz*Hn*Tlen*Dh)   // 6291456

// Scratch (allocation-free rule: __device__ globals)
__device__ float g_q[QKV_ELEMS];
__device__ float g_k[QKV_ELEMS];
__device__ float g_v[QKV_ELEMS];
__device__ float g_o[QKV_ELEMS];

// ---------------------------------------------------------------------------
// GEMM tiles
// ---------------------------------------------------------------------------
#define BM 128
#define BN 128
#define BK 16

// QKV projection: q/k/v[b,h,t,d] = sum_c x[b,t,c] * W[h,c,d]
// A = X [16384, 384] row-major; B = W viewed as [384, 384] with col j=(h*64+d)
__global__ __launch_bounds__(256) void qkv_kernel(
    const float* __restrict__ X,
    const float* __restrict__ Wq,
    const float* __restrict__ Wk,
    const float* __restrict__ Wv)
{
    const float* W = (blockIdx.z == 0) ? Wq : (blockIdx.z == 1) ? Wk : Wv;
    float* O = (blockIdx.z == 0) ? g_q : (blockIdx.z == 1) ? g_k : g_v;

    __shared__ __align__(16) float As[BK][BM + 4];
    __shared__ __align__(16) float Bs[BK][BN + 4];

    const int tid = threadIdx.x;
    const int blockM = blockIdx.y * BM;
    const int blockN = blockIdx.x * BN;

    const int aRow = tid >> 2;          // 0..63
    const int aK   = (tid & 3) * 4;     // 0,4,8,12
    const int bK   = tid >> 5;          // 0..7
    const int bN   = (tid & 31) * 4;    // 0..124

    const int trow = tid >> 4;          // 0..15
    const int tcol = tid & 15;          // 0..15

    float acc[8][8];
    #pragma unroll
    for (int i = 0; i < 8; i++)
        #pragma unroll
        for (int j = 0; j < 8; j++) acc[i][j] = 0.f;

    for (int kt = 0; kt < Cdim; kt += BK) {
        #pragma unroll
        for (int p = 0; p < 2; p++) {
            int m = aRow + 64 * p;
            float4 a = *(const float4*)&X[(size_t)(blockM + m) * Cdim + kt + aK];
            As[aK + 0][m] = a.x; As[aK + 1][m] = a.y;
            As[aK + 2][m] = a.z; As[aK + 3][m] = a.w;
        }
        #pragma unroll
        for (int p = 0; p < 2; p++) {
            int kk = bK + 8 * p;
            int n = blockN + bN;
            int h = n >> 6, d = n & 63;
            float4 b = *(const float4*)&W[((size_t)h * Cdim + kt + kk) * Dh + d];
            *(float4*)&Bs[kk][bN] = b;
        }
        __syncthreads();
        #pragma unroll
        for (int kk = 0; kk < BK; kk++) {
            float a[8], b[8];
            *(float4*)&a[0] = *(float4*)&As[kk][trow * 8];
            *(float4*)&a[4] = *(float4*)&As[kk][trow * 8 + 4];
            *(float4*)&b[0] = *(float4*)&Bs[kk][tcol * 8];
            *(float4*)&b[4] = *(float4*)&Bs[kk][tcol * 8 + 4];
            #pragma unroll
            for (int i = 0; i < 8; i++)
                #pragma unroll
                for (int j = 0; j < 8; j++)
                    acc[i][j] += a[i] * b[j];
        }
        __syncthreads();
    }

    // epilogue -> [B,H,T,D]
    #pragma unroll
    for (int i = 0; i < 8; i++) {
        int m = blockM + trow * 8 + i;
        int bb = m >> 8, t = m & 255;
        #pragma unroll
        for (int j4 = 0; j4 < 2; j4++) {
            int n = blockN + tcol * 8 + j4 * 4;
            int h = n >> 6, d = n & 63;
            float4 o;
            o.x = acc[i][j4 * 4 + 0]; o.y = acc[i][j4 * 4 + 1];
            o.z = acc[i][j4 * 4 + 2]; o.w = acc[i][j4 * 4 + 3];
            *(float4*)&O[(((size_t)bb * Hn + h) * Tlen + t) * Dh + d] = o;
        }
    }
}

// ---------------------------------------------------------------------------
// Fused causal attention: one CTA per (b,h). K padded [256][68] (conflict-free
// vectorized score LDS), V [256][64] (conflict-free float2 PV LDS).
// ---------------------------------------------------------------------------
#define KPAD 68
#define ATT_SMEM_BYTES ((Tlen*KPAD + Tlen*Dh + 8*Tlen) * 4)   // 143360

__global__ __launch_bounds__(256) void attn_kernel()
{
    extern __shared__ __align__(16) float sm[];
    float* Ks = sm;                           // [256][68]
    float* Vs = sm + Tlen * KPAD;             // [256][64]
    float* Ws = sm + Tlen * KPAD + Tlen * Dh; // [8][256] per-warp weights

    const int bh = blockIdx.x;
    const size_t base = (size_t)bh * (Tlen * Dh);
    const int tid = threadIdx.x;
    const int lane = tid & 31;
    const int warp = tid >> 5;

    // Stage K (padded) and V into smem; 4096 float4 total, 16 per thread.
    for (int u = tid; u < (Tlen * Dh) / 4; u += 256) {
        int j = u >> 4;        // row 0..255
        int d4 = u & 15;       // float4 col 0..15
        float4 kv = *(const float4*)&g_k[base + (size_t)u * 4];
        *(float4*)&Ks[j * KPAD + d4 * 4] = kv;
        float4 vv = *(const float4*)&g_v[base + (size_t)u * 4];
        *(float4*)&Vs[u * 4] = vv;
    }
    __syncthreads();

    const float scale = 0.125f;  // 1/sqrt(64)

    for (int r = warp; r < Tlen; r += 8) {
        // q row -> registers (warp-uniform broadcast loads)
        float qreg[64];
        const float* qp = &g_q[base + (size_t)r * Dh];
        #pragma unroll
        for (int t4 = 0; t4 < 16; t4++) {
            float4 qv = *(const float4*)&qp[t4 * 4];
            qreg[4 * t4 + 0] = qv.x; qreg[4 * t4 + 1] = qv.y;
            qreg[4 * t4 + 2] = qv.z; qreg[4 * t4 + 3] = qv.w;
        }

        float s[8];
        #pragma unroll
        for (int g = 0; g < 8; g++) s[g] = -INFINITY;

        const int ng = (r >> 5) + 1;   // warp-uniform causal group count
        for (int g = 0; g < ng; g++) {
            int j = g * 32 + lane;
            float a = 0.f;
            const float4* kr = (const float4*)&Ks[j * KPAD];
            #pragma unroll
            for (int t4 = 0; t4 < 16; t4++) {
                float4 kv = kr[t4];
                a += qreg[4 * t4 + 0] * kv.x + qreg[4 * t4 + 1] * kv.y
                   + qreg[4 * t4 + 2] * kv.z + qreg[4 * t4 + 3] * kv.w;
            }
            s[g] = (j <= r) ? a * scale : -INFINITY;
        }

        // warp softmax
        float m = s[0];
        #pragma unroll
        for (int g = 1; g < 8; g++) m = fmaxf(m, s[g]);
        #pragma unroll
        for (int off = 16; off; off >>= 1)
            m = fmaxf(m, __shfl_xor_sync(0xffffffffu, m, off));

        float p[8];
        float sum = 0.f;
        for (int g = 0; g < ng; g++) { p[g] = __expf(s[g] - m); sum += p[g]; }
        #pragma unroll
        for (int off = 16; off; off >>= 1)
            sum += __shfl_xor_sync(0xffffffffu, sum, off);
        float inv = 1.0f / sum;

        for (int g = 0; g < ng; g++)
            Ws[warp * 256 + g * 32 + lane] = p[g] * inv;
        __syncwarp();

        // PV: lane owns d = 2*lane, 2*lane+1
        float o0 = 0.f, o1 = 0.f;
        const float2* vp = (const float2*)Vs;
        #pragma unroll 4
        for (int j = 0; j <= r; j++) {
            float w = Ws[warp * 256 + j];
            float2 vv = vp[j * 32 + lane];
            o0 += w * vv.x;
            o1 += w * vv.y;
        }
        *(float2*)&g_o[base + (size_t)r * Dh + lane * 2] = make_float2(o0, o1);
        __syncwarp();   // WAR on Ws before next row
    }
}

// ---------------------------------------------------------------------------
// Output projection: out[m][n] = sum_k Oc[m][k] * Wp[n][k] + bp[n]
// A = concat(heads) of g_o (indexed), B = Wp^T.
// ---------------------------------------------------------------------------
__global__ __launch_bounds__(256) void proj_kernel(
    const float* __restrict__ Wp,
    const float* __restrict__ bp,
    float* __restrict__ out)
{
    __shared__ __align__(16) float As[BK][BM + 4];
    __shared__ __align__(16) float Bs[BK][BN + 4];

    const int tid = threadIdx.x;
    const int blockM = blockIdx.y * BM;
    const int blockN = blockIdx.x * BN;

    const int aRow = tid >> 2;
    const int aK   = (tid & 3) * 4;
    const int bRow = tid >> 2;         // n index 0..63
    const int bK4  = (tid & 3);        // k4 0..3 (k = 4*bK4)

    const int trow = tid >> 4;
    const int tcol = tid & 15;

    float acc[8][8];
    #pragma unroll
    for (int i = 0; i < 8; i++)
        #pragma unroll
        for (int j = 0; j < 8; j++) acc[i][j] = 0.f;

    for (int kt = 0; kt < Cdim; kt += BK) {
        // A tile from head-concat of g_o
        #pragma unroll
        for (int p = 0; p < 2; p++) {
            int m = blockM + aRow + 64 * p;
            int k = kt + aK;
            size_t addr = (((size_t)(m >> 8)) * Hn + (k >> 6)) * (Tlen * Dh)
                        + (size_t)(m & 255) * Dh + (k & 63);
            float4 a = *(const float4*)&g_o[addr];
            int mm = aRow + 64 * p;
            As[aK + 0][mm] = a.x; As[aK + 1][mm] = a.y;
            As[aK + 2][mm] = a.z; As[aK + 3][mm] = a.w;
        }
        // B tile: Bs[k][n] = Wp[n][k]
        #pragma unroll
        for (int p = 0; p < 2; p++) {
            int n = bRow + 64 * p;
            float4 b = *(const float4*)&Wp[(size_t)(blockN + n) * Cdim + kt + 4 * bK4];
            Bs[4 * bK4 + 0][n] = b.x; Bs[4 * bK4 + 1][n] = b.y;
            Bs[4 * bK4 + 2][n] = b.z; Bs[4 * bK4 + 3][n] = b.w;
        }
        __syncthreads();
        #pragma unroll
        for (int kk = 0; kk < BK; kk++) {
            float a[8], b[8];
            *(float4*)&a[0] = *(float4*)&As[kk][trow * 8];
            *(float4*)&a[4] = *(float4*)&As[kk][trow * 8 + 4];
            *(float4*)&b[0] = *(float4*)&Bs[kk][tcol * 8];
            *(float4*)&b[4] = *(float4*)&Bs[kk][tcol * 8 + 4];
            #pragma unroll
            for (int i = 0; i < 8; i++)
                #pragma unroll
                for (int j = 0; j < 8; j++)
                    acc[i][j] += a[i] * b[j];
        }
        __syncthreads();
    }

    #pragma unroll
    for (int i = 0; i < 8; i++) {
        int m = blockM + trow * 8 + i;
        #pragma unroll
        for (int j4 = 0; j4 < 2; j4++) {
            int n = blockN + tcol * 8 + j4 * 4;
            float4 bb = *(const float4*)&bp[n];
            float4 o;
            o.x = acc[i][j4 * 4 + 0] + bb.x;
            o.y = acc[i][j4 * 4 + 1] + bb.y;
            o.z = acc[i][j4 * 4 + 2] + bb.z;
            o.w = acc[i][j4 * 4 + 3] + bb.w;
            *(float4*)&out[(size_t)m * Cdim + n] = o;
        }
    }
}

// ---------------------------------------------------------------------------
extern "C" void kernel_launch(void* const* d_in, const int* in_sizes, int n_in,
                              void* d_out, int out_size)
{
    const float* x  = (const float*)d_in[0];
    const float* Wq = (const float*)d_in[1];
    const float* Wk = (const float*)d_in[2];
    const float* Wv = (const float*)d_in[3];
    const float* Wp = (const float*)d_in[4];
    const float* bp = (const float*)d_in[5];
    float* out = (float*)d_out;

    (void)in_sizes; (void)n_in; (void)out_size;

    cudaFuncSetAttribute(attn_kernel,
                         cudaFuncAttributeMaxDynamicSharedMemorySize,
                         ATT_SMEM_BYTES);

    qkv_kernel<<<dim3(3, 128, 3), 256>>>(x, Wq, Wk, Wv);
    attn_kernel<<<dim3(Bsz * Hn), 256, ATT_SMEM_BYTES>>>();
    proj_kernel<<<dim3(3, 128), 256>>>(Wp, bp, out);
}

// round 3
// speedup vs baseline: 2.1060x; 2.1060x over previous
#include <cuda_runtime.h>
#include <math.h>
#include <stdint.h>

#define Bsz  64
#define Tlen 256
#define Cdim 384
#define Hn   6
#define Dh   64
#define QKV_ELEMS (Bsz*Hn*Tlen*Dh)   // 6291456

__device__ float g_q[QKV_ELEMS];
__device__ float g_k[QKV_ELEMS];
__device__ float g_v[QKV_ELEMS];
__device__ float g_o[QKV_ELEMS];

// ---------------------------------------------------------------------------
// tf32 helpers
// ---------------------------------------------------------------------------
__device__ __forceinline__ uint32_t f2tf(float f) {
    uint32_t r;
    asm("cvt.rna.tf32.f32 %0, %1;" : "=r"(r) : "f"(f));
    return r;
}

__device__ __forceinline__ void mma_tf32(float d[4], const uint32_t a[4],
                                         const uint32_t b[2], const float c[4]) {
    asm volatile(
        "mma.sync.aligned.m16n8k8.row.col.f32.tf32.tf32.f32 "
        "{%0,%1,%2,%3}, {%4,%5,%6,%7}, {%8,%9}, {%10,%11,%12,%13};"
        : "=f"(d[0]), "=f"(d[1]), "=f"(d[2]), "=f"(d[3])
        : "r"(a[0]), "r"(a[1]), "r"(a[2]), "r"(a[3]),
          "r"(b[0]), "r"(b[1]),
          "f"(c[0]), "f"(c[1]), "f"(c[2]), "f"(c[3]));
}

// ---------------------------------------------------------------------------
// QKV projection with tf32 MMA.
// Global GEMM: [16384, 384] x [384, 1152] ; CTA tile 128x128, warp tile 64x32.
// blockIdx.x in [0,9): n-base = bx*128; matrix = n-base/384 (exact: 384=3*128)
// ---------------------------------------------------------------------------
#define GBM 128
#define GBN 128
#define GBK 32

__global__ __launch_bounds__(256, 2) void qkv_mma(
    const float* __restrict__ X,
    const float* __restrict__ Wq,
    const float* __restrict__ Wk,
    const float* __restrict__ Wv)
{
    __shared__ uint32_t As[GBM][36];   // [m][k], stride 36 -> conflict-free frags
    __shared__ uint32_t Bs[GBK][136];  // [k][n], stride 136 -> conflict-free frags

    const int tid  = threadIdx.x;
    const int lane = tid & 31;
    const int warp = tid >> 5;
    const int gq   = lane >> 2;   // groupID
    const int tg   = lane & 3;    // thread-in-group

    const int warpM = (warp >> 2) * 64;
    const int warpN = (warp & 3) * 32;

    const int nbase = blockIdx.x * GBN;          // 0..1024
    const int mat   = nbase / 384;               // 0,1,2
    const int nloc  = nbase - mat * 384;         // 0,128,256
    const float* __restrict__ W = (mat == 0) ? Wq : (mat == 1) ? Wk : Wv;
    float* __restrict__ O = (mat == 0) ? g_q : (mat == 1) ? g_k : g_v;

    const int blockM = blockIdx.y * GBM;

    float acc[4][4][4];
    #pragma unroll
    for (int mt = 0; mt < 4; mt++)
        #pragma unroll
        for (int nt = 0; nt < 4; nt++)
            #pragma unroll
            for (int i = 0; i < 4; i++) acc[mt][nt][i] = 0.f;

    const int arow = tid >> 3;            // 0..31
    const int akf  = (tid & 7) * 4;       // 0..28
    const int bk   = tid >> 5;            // 0..7
    const int bnf  = (tid & 31) * 4;      // 0..124

    for (int kt = 0; kt < Cdim; kt += GBK) {
        // A tile: X[blockM+m][kt+k]
        #pragma unroll
        for (int p = 0; p < 4; p++) {
            int m = arow + 32 * p;
            float4 v = *(const float4*)&X[(size_t)(blockM + m) * Cdim + kt + akf];
            As[m][akf + 0] = f2tf(v.x); As[m][akf + 1] = f2tf(v.y);
            As[m][akf + 2] = f2tf(v.z); As[m][akf + 3] = f2tf(v.w);
        }
        // B tile: Bs[k][n] = W[h][kt+k][d], n local in [0,128)
        #pragma unroll
        for (int p = 0; p < 4; p++) {
            int k  = bk + 8 * p;
            int nl = nloc + bnf;
            int h  = nl >> 6, d = nl & 63;
            float4 v = *(const float4*)&W[((size_t)h * Cdim + kt + k) * Dh + d];
            Bs[k][bnf + 0] = f2tf(v.x); Bs[k][bnf + 1] = f2tf(v.y);
            Bs[k][bnf + 2] = f2tf(v.z); Bs[k][bnf + 3] = f2tf(v.w);
        }
        __syncthreads();

        #pragma unroll
        for (int ks = 0; ks < 4; ks++) {
            const int k0 = ks * 8;
            uint32_t a[4][4];
            #pragma unroll
            for (int mt = 0; mt < 4; mt++) {
                int r0 = warpM + mt * 16 + gq;
                a[mt][0] = As[r0][k0 + tg];
                a[mt][1] = As[r0 + 8][k0 + tg];
                a[mt][2] = As[r0][k0 + tg + 4];
                a[mt][3] = As[r0 + 8][k0 + tg + 4];
            }
            uint32_t b[4][2];
            #pragma unroll
            for (int nt = 0; nt < 4; nt++) {
                int c0 = warpN + nt * 8 + gq;
                b[nt][0] = Bs[k0 + tg][c0];
                b[nt][1] = Bs[k0 + tg + 4][c0];
            }
            #pragma unroll
            for (int mt = 0; mt < 4; mt++)
                #pragma unroll
                for (int nt = 0; nt < 4; nt++)
                    mma_tf32(acc[mt][nt], a[mt], b[nt], acc[mt][nt]);
        }
        __syncthreads();
    }

    // epilogue -> [B,H,T,D]; C fragment rows are gq (c0,c1) and gq+8 (c2,c3)
    #pragma unroll
    for (int mt = 0; mt < 4; mt++) {
        #pragma unroll
        for (int nt = 0; nt < 4; nt++) {
            int cloc = nloc + warpN + nt * 8 + 2 * tg;
            int h = cloc >> 6, d = cloc & 63;
            int r = blockM + warpM + mt * 16 + gq;
            int bb = r >> 8, t = r & 255;
            float2 v0 = make_float2(acc[mt][nt][0], acc[mt][nt][1]);
            *(float2*)&O[(((size_t)bb * Hn + h) * Tlen + t) * Dh + d] = v0;
            float2 v1 = make_float2(acc[mt][nt][2], acc[mt][nt][3]);
            *(float2*)&O[(((size_t)bb * Hn + h) * Tlen + (t + 8)) * Dh + d] = v1;
        }
    }
}

// ---------------------------------------------------------------------------
// Output projection with tf32 MMA: out[m][n] = sum_k Oc[m][k]*Wp[n][k] + bp[n]
// ---------------------------------------------------------------------------
__global__ __launch_bounds__(256, 2) void proj_mma(
    const float* __restrict__ Wp,
    const float* __restrict__ bp,
    float* __restrict__ out)
{
    __shared__ uint32_t As[GBM][36];
    __shared__ uint32_t Bs[GBK][136];

    const int tid  = threadIdx.x;
    const int lane = tid & 31;
    const int warp = tid >> 5;
    const int gq   = lane >> 2;
    const int tg   = lane & 3;
    const int warpM = (warp >> 2) * 64;
    const int warpN = (warp & 3) * 32;

    const int blockN = blockIdx.x * GBN;
    const int blockM = blockIdx.y * GBM;

    float acc[4][4][4];
    #pragma unroll
    for (int mt = 0; mt < 4; mt++)
        #pragma unroll
        for (int nt = 0; nt < 4; nt++)
            #pragma unroll
            for (int i = 0; i < 4; i++) acc[mt][nt][i] = 0.f;

    const int arow = tid >> 3;
    const int akf  = (tid & 7) * 4;
    const int bn   = tid & 31;       // n index per pass
    const int bkf  = (tid >> 5) * 4; // k = bkf..bkf+3

    for (int kt = 0; kt < Cdim; kt += GBK) {
        // A tile from head-concat g_o: k -> (h, d)
        #pragma unroll
        for (int p = 0; p < 4; p++) {
            int m = arow + 32 * p;
            int mg = blockM + m;
            int kg = kt + akf;
            size_t addr = (((size_t)(mg >> 8)) * Hn + (kg >> 6)) * (Tlen * Dh)
                        + (size_t)(mg & 255) * Dh + (kg & 63);
            float4 v = *(const float4*)&g_o[addr];
            As[m][akf + 0] = f2tf(v.x); As[m][akf + 1] = f2tf(v.y);
            As[m][akf + 2] = f2tf(v.z); As[m][akf + 3] = f2tf(v.w);
        }
        // B tile: Bs[k][n] = Wp[blockN+n][kt+k]
        #pragma unroll
        for (int p = 0; p < 4; p++) {
            int n = bn + 32 * p;
            float4 v = *(const float4*)&Wp[(size_t)(blockN + n) * Cdim + kt + bkf];
            Bs[bkf + 0][n] = f2tf(v.x); Bs[bkf + 1][n] = f2tf(v.y);
            Bs[bkf + 2][n] = f2tf(v.z); Bs[bkf + 3][n] = f2tf(v.w);
        }
        __syncthreads();

        #pragma unroll
        for (int ks = 0; ks < 4; ks++) {
            const int k0 = ks * 8;
            uint32_t a[4][4];
            #pragma unroll
            for (int mt = 0; mt < 4; mt++) {
                int r0 = warpM + mt * 16 + gq;
                a[mt][0] = As[r0][k0 + tg];
                a[mt][1] = As[r0 + 8][k0 + tg];
                a[mt][2] = As[r0][k0 + tg + 4];
                a[mt][3] = As[r0 + 8][k0 + tg + 4];
            }
            uint32_t b[4][2];
            #pragma unroll
            for (int nt = 0; nt < 4; nt++) {
                int c0 = warpN + nt * 8 + gq;
                b[nt][0] = Bs[k0 + tg][c0];
                b[nt][1] = Bs[k0 + tg + 4][c0];
            }
            #pragma unroll
            for (int mt = 0; mt < 4; mt++)
                #pragma unroll
                for (int nt = 0; nt < 4; nt++)
                    mma_tf32(acc[mt][nt], a[mt], b[nt], acc[mt][nt]);
        }
        __syncthreads();
    }

    // C fragment rows: gq (c0,c1) and gq+8 (c2,c3)
    #pragma unroll
    for (int mt = 0; mt < 4; mt++) {
        #pragma unroll
        for (int nt = 0; nt < 4; nt++) {
            int n = blockN + warpN + nt * 8 + 2 * tg;
            float b0 = bp[n], b1 = bp[n + 1];
            int r = blockM + warpM + mt * 16 + gq;
            float2 v0 = make_float2(acc[mt][nt][0] + b0, acc[mt][nt][1] + b1);
            *(float2*)&out[(size_t)r * Cdim + n] = v0;
            float2 v1 = make_float2(acc[mt][nt][2] + b0, acc[mt][nt][3] + b1);
            *(float2*)&out[(size_t)(r + 8) * Cdim + n] = v1;
        }
    }
}

// ---------------------------------------------------------------------------
// Attention: one CTA per (b,h). Block-GEMM structure:
//   Kt[d][s] (64 x 260), Vs[s][d] (256 x 68), per q-tile Qt[d][m] (64 x 68),
//   S = Q K^T in registers (warp owns 8 m-rows; softmax via warp shuffles),
//   P -> Ps[m][s] (64 x 260), O = P V with warp-uniform causal bound.
// ---------------------------------------------------------------------------
#define KT_STRIDE 260
#define VS_STRIDE 68
#define QT_STRIDE 68
#define PS_STRIDE 260
#define SM_KT 0
#define SM_VS (SM_KT + 64 * KT_STRIDE)            // 16640
#define SM_QT (SM_VS + 256 * VS_STRIDE)           // 34048
#define SM_PS (SM_QT + 64 * QT_STRIDE)            // 38400
#define ATT_SMEM_FLOATS (SM_PS + 64 * PS_STRIDE)  // 55040
#define ATT_SMEM_BYTES (ATT_SMEM_FLOATS * 4)      // 220160

__global__ __launch_bounds__(256) void attn2_kernel()
{
    extern __shared__ __align__(16) float sm[];
    float* Kt = sm + SM_KT;
    float* Vs = sm + SM_VS;
    float* Qt = sm + SM_QT;
    float* Ps = sm + SM_PS;

    const int bh = blockIdx.x;
    const size_t base = (size_t)bh * (Tlen * Dh);
    const int tid  = threadIdx.x;
    const int lane = tid & 31;
    const int warp = tid >> 5;

    // --- Load K transposed: Kt[d][s] ---
    {
        int s0 = tid & 31;
        int d4b = tid >> 5;   // 0..7
        #pragma unroll
        for (int it = 0; it < 16; it++) {
            int d4 = d4b + 8 * (it & 1);
            int s  = s0 + 32 * (it >> 1);
            float4 v = *(const float4*)&g_k[base + (size_t)s * Dh + d4 * 4];
            Kt[(4 * d4 + 0) * KT_STRIDE + s] = v.x;
            Kt[(4 * d4 + 1) * KT_STRIDE + s] = v.y;
            Kt[(4 * d4 + 2) * KT_STRIDE + s] = v.z;
            Kt[(4 * d4 + 3) * KT_STRIDE + s] = v.w;
        }
    }
    // --- Load V natural: Vs[s][d] ---
    #pragma unroll
    for (int it = 0; it < 16; it++) {
        int idx = tid + 256 * it;        // float4 index in [0,4096)
        int s = idx >> 4, d4 = idx & 15;
        float4 v = *(const float4*)&g_v[base + (size_t)idx * 4];
        *(float4*)&Vs[s * VS_STRIDE + d4 * 4] = v;
    }
    __syncthreads();

    const float scale = 0.125f;
    const int ty2 = tid >> 4;   // 0..15 (PV m)
    const int tx2 = tid & 15;   // 0..15 (PV d)

    for (int qi = 0; qi < 4; qi++) {
        const int m0 = qi * 64;

        // --- Load Q tile transposed: Qt[d][m] ---
        #pragma unroll
        for (int it = 0; it < 4; it++) {
            int idx = tid + 256 * it;    // [0,1024)
            int m = idx & 63, d4 = idx >> 6;
            float4 v = *(const float4*)&g_q[base + (size_t)(m0 + m) * Dh + d4 * 4];
            Qt[(4 * d4 + 0) * QT_STRIDE + m] = v.x;
            Qt[(4 * d4 + 1) * QT_STRIDE + m] = v.y;
            Qt[(4 * d4 + 2) * QT_STRIDE + m] = v.z;
            Qt[(4 * d4 + 3) * QT_STRIDE + m] = v.w;
        }
        __syncthreads();

        // --- S = Q K^T : warp owns rows [warp*8, warp*8+8), lane owns s = lane*8..+7
        float s_acc[8][8];
        #pragma unroll
        for (int i = 0; i < 8; i++)
            #pragma unroll
            for (int j = 0; j < 8; j++) s_acc[i][j] = 0.f;

        const int mrow = warp * 8;
        #pragma unroll 4
        for (int k = 0; k < Dh; k++) {
            float a[8], b[8];
            *(float4*)&a[0] = *(float4*)&Qt[k * QT_STRIDE + mrow];
            *(float4*)&a[4] = *(float4*)&Qt[k * QT_STRIDE + mrow + 4];
            *(float4*)&b[0] = *(float4*)&Kt[k * KT_STRIDE + lane * 8];
            *(float4*)&b[4] = *(float4*)&Kt[k * KT_STRIDE + lane * 8 + 4];
            #pragma unroll
            for (int i = 0; i < 8; i++)
                #pragma unroll
                for (int j = 0; j < 8; j++)
                    s_acc[i][j] += a[i] * b[j];
        }

        // --- causal mask + softmax per row (warp-wide) ---
        #pragma unroll
        for (int i = 0; i < 8; i++) {
            int mg = m0 + mrow + i;
            float mx = -INFINITY;
            #pragma unroll
            for (int j = 0; j < 8; j++) {
                float v = (lane * 8 + j <= mg) ? s_acc[i][j] * scale : -INFINITY;
                s_acc[i][j] = v;
                mx = fmaxf(mx, v);
            }
            #pragma unroll
            for (int off = 16; off; off >>= 1)
                mx = fmaxf(mx, __shfl_xor_sync(0xffffffffu, mx, off));
            float sum = 0.f;
            #pragma unroll
            for (int j = 0; j < 8; j++) {
                float p = __expf(s_acc[i][j] - mx);
                s_acc[i][j] = p;
                sum += p;
            }
            #pragma unroll
            for (int off = 16; off; off >>= 1)
                sum += __shfl_xor_sync(0xffffffffu, sum, off);
            float inv = 1.0f / sum;
            #pragma unroll
            for (int j = 0; j < 8; j++) s_acc[i][j] *= inv;
        }

        // --- write P: Ps[m][s] ---
        #pragma unroll
        for (int i = 0; i < 8; i++) {
            *(float4*)&Ps[(mrow + i) * PS_STRIDE + lane * 8]     = *(float4*)&s_acc[i][0];
            *(float4*)&Ps[(mrow + i) * PS_STRIDE + lane * 8 + 4] = *(float4*)&s_acc[i][4];
        }
        __syncthreads();

        // --- O = P V, causal bound s < m0+64 (warp-uniform) ---
        const int s_max = m0 + 64;
        float o[4][4];
        #pragma unroll
        for (int i = 0; i < 4; i++)
            #pragma unroll
            for (int j = 0; j < 4; j++) o[i][j] = 0.f;

        #pragma unroll 4
        for (int s = 0; s < s_max; s++) {
            float a0 = Ps[(ty2 * 4 + 0) * PS_STRIDE + s];
            float a1 = Ps[(ty2 * 4 + 1) * PS_STRIDE + s];
            float a2 = Ps[(ty2 * 4 + 2) * PS_STRIDE + s];
            float a3 = Ps[(ty2 * 4 + 3) * PS_STRIDE + s];
            float4 bv = *(float4*)&Vs[s * VS_STRIDE + tx2 * 4];
            o[0][0] += a0 * bv.x; o[0][1] += a0 * bv.y; o[0][2] += a0 * bv.z; o[0][3] += a0 * bv.w;
            o[1][0] += a1 * bv.x; o[1][1] += a1 * bv.y; o[1][2] += a1 * bv.z; o[1][3] += a1 * bv.w;
            o[2][0] += a2 * bv.x; o[2][1] += a2 * bv.y; o[2][2] += a2 * bv.z; o[2][3] += a2 * bv.w;
            o[3][0] += a3 * bv.x; o[3][1] += a3 * bv.y; o[3][2] += a3 * bv.z; o[3][3] += a3 * bv.w;
        }

        #pragma unroll
        for (int i = 0; i < 4; i++) {
            float4 v = make_float4(o[i][0], o[i][1], o[i][2], o[i][3]);
            *(float4*)&g_o[base + (size_t)(m0 + ty2 * 4 + i) * Dh + tx2 * 4] = v;
        }
        __syncthreads();   // protect Qt/Ps for next iteration
    }
}

// ---------------------------------------------------------------------------
extern "C" void kernel_launch(void* const* d_in, const int* in_sizes, int n_in,
                              void* d_out, int out_size)
{
    const float* x  = (const float*)d_in[0];
    const float* Wq = (const float*)d_in[1];
    const float* Wk = (const float*)d_in[2];
    const float* Wv = (const float*)d_in[3];
    const float* Wp = (const float*)d_in[4];
    const float* bp = (const float*)d_in[5];
    float* out = (float*)d_out;

    (void)in_sizes; (void)n_in; (void)out_size;

    cudaFuncSetAttribute(attn2_kernel,
                         cudaFuncAttributeMaxDynamicSharedMemorySize,
                         ATT_SMEM_BYTES);

    qkv_mma<<<dim3(9, 128), 256>>>(x, Wq, Wk, Wv);
    attn2_kernel<<<dim3(Bsz * Hn), 256, ATT_SMEM_BYTES>>>();
    proj_mma<<<dim3(3, 128), 256>>>(Wp, bp, out);
}

// round 4
// speedup vs baseline: 3.3072x; 1.5704x over previous
#include <cuda_runtime.h>
#include <math.h>
#include <stdint.h>

#define Bsz  64
#define Tlen 256
#define Cdim 384
#define Hn   6
#define Dh   64
#define QKV_ELEMS (Bsz*Hn*Tlen*Dh)   // 6291456

__device__ float g_q[QKV_ELEMS];
__device__ float g_k[QKV_ELEMS];
__device__ float g_v[QKV_ELEMS];
__device__ float g_o[QKV_ELEMS];

// ---------------------------------------------------------------------------
// tf32 helpers
// ---------------------------------------------------------------------------
__device__ __forceinline__ uint32_t f2tf(float f) {
    uint32_t r;
    asm("cvt.rna.tf32.f32 %0, %1;" : "=r"(r) : "f"(f));
    return r;
}

__device__ __forceinline__ void mma_tf32(float d[4], const uint32_t a[4],
                                         const uint32_t b[2], const float c[4]) {
    asm volatile(
        "mma.sync.aligned.m16n8k8.row.col.f32.tf32.tf32.f32 "
        "{%0,%1,%2,%3}, {%4,%5,%6,%7}, {%8,%9}, {%10,%11,%12,%13};"
        : "=f"(d[0]), "=f"(d[1]), "=f"(d[2]), "=f"(d[3])
        : "r"(a[0]), "r"(a[1]), "r"(a[2]), "r"(a[3]),
          "r"(b[0]), "r"(b[1]),
          "f"(c[0]), "f"(c[1]), "f"(c[2]), "f"(c[3]));
}

// ---------------------------------------------------------------------------
// QKV projection with tf32 MMA (unchanged from round 3).
// ---------------------------------------------------------------------------
#define GBM 128
#define GBN 128
#define GBK 32

__global__ __launch_bounds__(256, 2) void qkv_mma(
    const float* __restrict__ X,
    const float* __restrict__ Wq,
    const float* __restrict__ Wk,
    const float* __restrict__ Wv)
{
    __shared__ uint32_t As[GBM][36];
    __shared__ uint32_t Bs[GBK][136];

    const int tid  = threadIdx.x;
    const int lane = tid & 31;
    const int warp = tid >> 5;
    const int gq   = lane >> 2;
    const int tg   = lane & 3;

    const int warpM = (warp >> 2) * 64;
    const int warpN = (warp & 3) * 32;

    const int nbase = blockIdx.x * GBN;
    const int mat   = nbase / 384;
    const int nloc  = nbase - mat * 384;
    const float* __restrict__ W = (mat == 0) ? Wq : (mat == 1) ? Wk : Wv;
    float* __restrict__ O = (mat == 0) ? g_q : (mat == 1) ? g_k : g_v;

    const int blockM = blockIdx.y * GBM;

    float acc[4][4][4];
    #pragma unroll
    for (int mt = 0; mt < 4; mt++)
        #pragma unroll
        for (int nt = 0; nt < 4; nt++)
            #pragma unroll
            for (int i = 0; i < 4; i++) acc[mt][nt][i] = 0.f;

    const int arow = tid >> 3;
    const int akf  = (tid & 7) * 4;
    const int bk   = tid >> 5;
    const int bnf  = (tid & 31) * 4;

    for (int kt = 0; kt < Cdim; kt += GBK) {
        #pragma unroll
        for (int p = 0; p < 4; p++) {
            int m = arow + 32 * p;
            float4 v = *(const float4*)&X[(size_t)(blockM + m) * Cdim + kt + akf];
            As[m][akf + 0] = f2tf(v.x); As[m][akf + 1] = f2tf(v.y);
            As[m][akf + 2] = f2tf(v.z); As[m][akf + 3] = f2tf(v.w);
        }
        #pragma unroll
        for (int p = 0; p < 4; p++) {
            int k  = bk + 8 * p;
            int nl = nloc + bnf;
            int h  = nl >> 6, d = nl & 63;
            float4 v = *(const float4*)&W[((size_t)h * Cdim + kt + k) * Dh + d];
            Bs[k][bnf + 0] = f2tf(v.x); Bs[k][bnf + 1] = f2tf(v.y);
            Bs[k][bnf + 2] = f2tf(v.z); Bs[k][bnf + 3] = f2tf(v.w);
        }
        __syncthreads();

        #pragma unroll
        for (int ks = 0; ks < 4; ks++) {
            const int k0 = ks * 8;
            uint32_t a[4][4];
            #pragma unroll
            for (int mt = 0; mt < 4; mt++) {
                int r0 = warpM + mt * 16 + gq;
                a[mt][0] = As[r0][k0 + tg];
                a[mt][1] = As[r0 + 8][k0 + tg];
                a[mt][2] = As[r0][k0 + tg + 4];
                a[mt][3] = As[r0 + 8][k0 + tg + 4];
            }
            uint32_t b[4][2];
            #pragma unroll
            for (int nt = 0; nt < 4; nt++) {
                int c0 = warpN + nt * 8 + gq;
                b[nt][0] = Bs[k0 + tg][c0];
                b[nt][1] = Bs[k0 + tg + 4][c0];
            }
            #pragma unroll
            for (int mt = 0; mt < 4; mt++)
                #pragma unroll
                for (int nt = 0; nt < 4; nt++)
                    mma_tf32(acc[mt][nt], a[mt], b[nt], acc[mt][nt]);
        }
        __syncthreads();
    }

    #pragma unroll
    for (int mt = 0; mt < 4; mt++) {
        #pragma unroll
        for (int nt = 0; nt < 4; nt++) {
            int cloc = nloc + warpN + nt * 8 + 2 * tg;
            int h = cloc >> 6, d = cloc & 63;
            int r = blockM + warpM + mt * 16 + gq;
            int bb = r >> 8, t = r & 255;
            float2 v0 = make_float2(acc[mt][nt][0], acc[mt][nt][1]);
            *(float2*)&O[(((size_t)bb * Hn + h) * Tlen + t) * Dh + d] = v0;
            float2 v1 = make_float2(acc[mt][nt][2], acc[mt][nt][3]);
            *(float2*)&O[(((size_t)bb * Hn + h) * Tlen + (t + 8)) * Dh + d] = v1;
        }
    }
}

// ---------------------------------------------------------------------------
// Output projection with tf32 MMA (unchanged from round 3).
// ---------------------------------------------------------------------------
__global__ __launch_bounds__(256, 2) void proj_mma(
    const float* __restrict__ Wp,
    const float* __restrict__ bp,
    float* __restrict__ out)
{
    __shared__ uint32_t As[GBM][36];
    __shared__ uint32_t Bs[GBK][136];

    const int tid  = threadIdx.x;
    const int lane = tid & 31;
    const int warp = tid >> 5;
    const int gq   = lane >> 2;
    const int tg   = lane & 3;
    const int warpM = (warp >> 2) * 64;
    const int warpN = (warp & 3) * 32;

    const int blockN = blockIdx.x * GBN;
    const int blockM = blockIdx.y * GBM;

    float acc[4][4][4];
    #pragma unroll
    for (int mt = 0; mt < 4; mt++)
        #pragma unroll
        for (int nt = 0; nt < 4; nt++)
            #pragma unroll
            for (int i = 0; i < 4; i++) acc[mt][nt][i] = 0.f;

    const int arow = tid >> 3;
    const int akf  = (tid & 7) * 4;
    const int bn   = tid & 31;
    const int bkf  = (tid >> 5) * 4;

    for (int kt = 0; kt < Cdim; kt += GBK) {
        #pragma unroll
        for (int p = 0; p < 4; p++) {
            int m = arow + 32 * p;
            int mg = blockM + m;
            int kg = kt + akf;
            size_t addr = (((size_t)(mg >> 8)) * Hn + (kg >> 6)) * (Tlen * Dh)
                        + (size_t)(mg & 255) * Dh + (kg & 63);
            float4 v = *(const float4*)&g_o[addr];
            As[m][akf + 0] = f2tf(v.x); As[m][akf + 1] = f2tf(v.y);
            As[m][akf + 2] = f2tf(v.z); As[m][akf + 3] = f2tf(v.w);
        }
        #pragma unroll
        for (int p = 0; p < 4; p++) {
            int n = bn + 32 * p;
            float4 v = *(const float4*)&Wp[(size_t)(blockN + n) * Cdim + kt + bkf];
            Bs[bkf + 0][n] = f2tf(v.x); Bs[bkf + 1][n] = f2tf(v.y);
            Bs[bkf + 2][n] = f2tf(v.z); Bs[bkf + 3][n] = f2tf(v.w);
        }
        __syncthreads();

        #pragma unroll
        for (int ks = 0; ks < 4; ks++) {
            const int k0 = ks * 8;
            uint32_t a[4][4];
            #pragma unroll
            for (int mt = 0; mt < 4; mt++) {
                int r0 = warpM + mt * 16 + gq;
                a[mt][0] = As[r0][k0 + tg];
                a[mt][1] = As[r0 + 8][k0 + tg];
                a[mt][2] = As[r0][k0 + tg + 4];
                a[mt][3] = As[r0 + 8][k0 + tg + 4];
            }
            uint32_t b[4][2];
            #pragma unroll
            for (int nt = 0; nt < 4; nt++) {
                int c0 = warpN + nt * 8 + gq;
                b[nt][0] = Bs[k0 + tg][c0];
                b[nt][1] = Bs[k0 + tg + 4][c0];
            }
            #pragma unroll
            for (int mt = 0; mt < 4; mt++)
                #pragma unroll
                for (int nt = 0; nt < 4; nt++)
                    mma_tf32(acc[mt][nt], a[mt], b[nt], acc[mt][nt]);
        }
        __syncthreads();
    }

    #pragma unroll
    for (int mt = 0; mt < 4; mt++) {
        #pragma unroll
        for (int nt = 0; nt < 4; nt++) {
            int n = blockN + warpN + nt * 8 + 2 * tg;
            float b0 = bp[n], b1 = bp[n + 1];
            int r = blockM + warpM + mt * 16 + gq;
            float2 v0 = make_float2(acc[mt][nt][0] + b0, acc[mt][nt][1] + b1);
            *(float2*)&out[(size_t)r * Cdim + n] = v0;
            float2 v1 = make_float2(acc[mt][nt][2] + b0, acc[mt][nt][3] + b1);
            *(float2*)&out[(size_t)(r + 8) * Cdim + n] = v1;
        }
    }
}

// ---------------------------------------------------------------------------
// Flash-style tensor-core attention. One CTA per (b,h), 8 warps.
//  Kt[d][s] (64x264 tf32), Vs[s][d] (256x72), Qs[m][d] (128x68), Ps[m][s] (128x68).
//  Q-tile 128 rows x 2; s-blocks of 64 with online softmax.
//  Warp w owns rows [16w,16w+16): S, softmax, P, PV all warp-local.
// ---------------------------------------------------------------------------
#define KTS 264
#define VSS 72
#define QSS 68
#define PSS 68
#define OFF_KT 0
#define OFF_VS (OFF_KT + 64 * KTS)              // 16896
#define OFF_QS (OFF_VS + 256 * VSS)             // 35328
#define OFF_PS (OFF_QS + 128 * QSS)             // 44032
#define ATT3_SMEM_WORDS (OFF_PS + 128 * PSS)    // 52736
#define ATT3_SMEM_BYTES (ATT3_SMEM_WORDS * 4)   // 210944

__global__ __launch_bounds__(256) void attn3_kernel()
{
    extern __shared__ __align__(16) uint32_t smu[];
    uint32_t* Kt = smu + OFF_KT;
    uint32_t* Vs = smu + OFF_VS;
    uint32_t* Qs = smu + OFF_QS;
    uint32_t* Ps = smu + OFF_PS;

    const int bh = blockIdx.x;
    const size_t base = (size_t)bh * (Tlen * Dh);
    const int tid  = threadIdx.x;
    const int lane = tid & 31;
    const int warp = tid >> 5;
    const int gq   = lane >> 2;
    const int tg   = lane & 3;
    const int wrow = warp * 16;

    // --- Stage K transposed: Kt[d][s] (scattered LDG, conflict-free STS) ---
    {
        const int s0  = tid & 31;
        const int d4b = tid >> 5;   // 0..7
        #pragma unroll
        for (int it = 0; it < 16; it++) {
            int d4 = d4b + 8 * (it & 1);
            int s  = s0 + 32 * (it >> 1);
            float4 v = *(const float4*)&g_k[base + (size_t)s * Dh + d4 * 4];
            Kt[(4 * d4 + 0) * KTS + s] = f2tf(v.x);
            Kt[(4 * d4 + 1) * KTS + s] = f2tf(v.y);
            Kt[(4 * d4 + 2) * KTS + s] = f2tf(v.z);
            Kt[(4 * d4 + 3) * KTS + s] = f2tf(v.w);
        }
    }
    // --- Stage V natural: Vs[s][d] (coalesced) ---
    #pragma unroll
    for (int it = 0; it < 16; it++) {
        int idx = tid + 256 * it;        // float4 index, [0,4096)
        int s = idx >> 4, d4 = idx & 15;
        float4 v = *(const float4*)&g_v[base + (size_t)idx * 4];
        uint4 u = make_uint4(f2tf(v.x), f2tf(v.y), f2tf(v.z), f2tf(v.w));
        *(uint4*)&Vs[s * VSS + 4 * d4] = u;
    }

    const float scale = 0.125f;

    for (int qi = 0; qi < 2; qi++) {
        __syncthreads();   // all warps done with previous Qs/Ps + first-iter staging
        // --- Stage Q tile: Qs[m][d] (coalesced) ---
        #pragma unroll
        for (int it = 0; it < 8; it++) {
            int idx = tid + 256 * it;    // [0,2048)
            int m = idx >> 4, d4 = idx & 15;
            float4 v = *(const float4*)&g_q[base + (size_t)(qi * 128 + m) * Dh + 4 * d4];
            uint4 u = make_uint4(f2tf(v.x), f2tf(v.y), f2tf(v.z), f2tf(v.w));
            *(uint4*)&Qs[m * QSS + 4 * d4] = u;
        }
        __syncthreads();

        const int row0 = qi * 128 + wrow + gq;
        const int row1 = row0 + 8;
        const int rowmax_warp = qi * 128 + wrow + 15;

        float m0r = -INFINITY, m1r = -INFINITY;
        float l0 = 0.f, l1 = 0.f;
        float o[8][4];
        #pragma unroll
        for (int nt = 0; nt < 8; nt++)
            #pragma unroll
            for (int c = 0; c < 4; c++) o[nt][c] = 0.f;

        const int nblocks = 2 * qi + 2;
        for (int sb = 0; sb < nblocks; sb++) {
            if (sb * 64 > rowmax_warp) continue;   // fully masked for this warp

            // ---- S = Q K^T (this warp's 16 rows x 64 cols) ----
            float sacc[8][4];
            #pragma unroll
            for (int nt = 0; nt < 8; nt++)
                #pragma unroll
                for (int c = 0; c < 4; c++) sacc[nt][c] = 0.f;

            #pragma unroll
            for (int ks = 0; ks < 8; ks++) {
                const int kk = ks * 8;
                uint32_t a[4];
                a[0] = Qs[(wrow + gq) * QSS + kk + tg];
                a[1] = Qs[(wrow + gq + 8) * QSS + kk + tg];
                a[2] = Qs[(wrow + gq) * QSS + kk + tg + 4];
                a[3] = Qs[(wrow + gq + 8) * QSS + kk + tg + 4];
                #pragma unroll
                for (int nt = 0; nt < 8; nt++) {
                    uint32_t b[2];
                    const int cc = sb * 64 + nt * 8 + gq;
                    b[0] = Kt[(kk + tg) * KTS + cc];
                    b[1] = Kt[(kk + tg + 4) * KTS + cc];
                    mma_tf32(sacc[nt], a, b, sacc[nt]);
                }
            }

            // ---- mask + online softmax ----
            float bm0 = -INFINITY, bm1 = -INFINITY;
            #pragma unroll
            for (int nt = 0; nt < 8; nt++) {
                const int c0 = sb * 64 + nt * 8 + 2 * tg;
                float v00 = (c0     <= row0) ? sacc[nt][0] * scale : -INFINITY;
                float v01 = (c0 + 1 <= row0) ? sacc[nt][1] * scale : -INFINITY;
                float v10 = (c0     <= row1) ? sacc[nt][2] * scale : -INFINITY;
                float v11 = (c0 + 1 <= row1) ? sacc[nt][3] * scale : -INFINITY;
                sacc[nt][0] = v00; sacc[nt][1] = v01;
                sacc[nt][2] = v10; sacc[nt][3] = v11;
                bm0 = fmaxf(bm0, fmaxf(v00, v01));
                bm1 = fmaxf(bm1, fmaxf(v10, v11));
            }
            bm0 = fmaxf(bm0, __shfl_xor_sync(0xffffffffu, bm0, 1));
            bm0 = fmaxf(bm0, __shfl_xor_sync(0xffffffffu, bm0, 2));
            bm1 = fmaxf(bm1, __shfl_xor_sync(0xffffffffu, bm1, 1));
            bm1 = fmaxf(bm1, __shfl_xor_sync(0xffffffffu, bm1, 2));

            const float mn0 = fmaxf(m0r, bm0);
            const float mn1 = fmaxf(m1r, bm1);
            const float cor0 = __expf(m0r - mn0);
            const float cor1 = __expf(m1r - mn1);
            m0r = mn0; m1r = mn1;

            float rs0 = 0.f, rs1 = 0.f;
            #pragma unroll
            for (int nt = 0; nt < 8; nt++) {
                float p00 = __expf(sacc[nt][0] - mn0);
                float p01 = __expf(sacc[nt][1] - mn0);
                float p10 = __expf(sacc[nt][2] - mn1);
                float p11 = __expf(sacc[nt][3] - mn1);
                rs0 += p00 + p01;
                rs1 += p10 + p11;
                uint2 u0 = make_uint2(f2tf(p00), f2tf(p01));
                *(uint2*)&Ps[(wrow + gq) * PSS + nt * 8 + 2 * tg] = u0;
                uint2 u1 = make_uint2(f2tf(p10), f2tf(p11));
                *(uint2*)&Ps[(wrow + gq + 8) * PSS + nt * 8 + 2 * tg] = u1;
            }
            rs0 += __shfl_xor_sync(0xffffffffu, rs0, 1);
            rs0 += __shfl_xor_sync(0xffffffffu, rs0, 2);
            rs1 += __shfl_xor_sync(0xffffffffu, rs1, 1);
            rs1 += __shfl_xor_sync(0xffffffffu, rs1, 2);
            l0 = l0 * cor0 + rs0;
            l1 = l1 * cor1 + rs1;

            #pragma unroll
            for (int nt = 0; nt < 8; nt++) {
                o[nt][0] *= cor0; o[nt][1] *= cor0;
                o[nt][2] *= cor1; o[nt][3] *= cor1;
            }
            __syncwarp();

            // ---- O += P V ----
            #pragma unroll
            for (int ks = 0; ks < 8; ks++) {
                const int kk = ks * 8;
                uint32_t a[4];
                a[0] = Ps[(wrow + gq) * PSS + kk + tg];
                a[1] = Ps[(wrow + gq + 8) * PSS + kk + tg];
                a[2] = Ps[(wrow + gq) * PSS + kk + tg + 4];
                a[3] = Ps[(wrow + gq + 8) * PSS + kk + tg + 4];
                #pragma unroll
                for (int nt = 0; nt < 8; nt++) {
                    uint32_t b[2];
                    b[0] = Vs[(sb * 64 + kk + tg) * VSS + nt * 8 + gq];
                    b[1] = Vs[(sb * 64 + kk + tg + 4) * VSS + nt * 8 + gq];
                    mma_tf32(o[nt], a, b, o[nt]);
                }
            }
            __syncwarp();   // Ps reuse next block (same warp rows)
        }

        // ---- finalize: divide by l, write out ----
        const float inv0 = 1.0f / l0;
        const float inv1 = 1.0f / l1;
        #pragma unroll
        for (int nt = 0; nt < 8; nt++) {
            const int col = nt * 8 + 2 * tg;
            float2 v0 = make_float2(o[nt][0] * inv0, o[nt][1] * inv0);
            *(float2*)&g_o[base + (size_t)row0 * Dh + col] = v0;
            float2 v1 = make_float2(o[nt][2] * inv1, o[nt][3] * inv1);
            *(float2*)&g_o[base + (size_t)row1 * Dh + col] = v1;
        }
    }
}

// ---------------------------------------------------------------------------
extern "C" void kernel_launch(void* const* d_in, const int* in_sizes, int n_in,
                              void* d_out, int out_size)
{
    const float* x  = (const float*)d_in[0];
    const float* Wq = (const float*)d_in[1];
    const float* Wk = (const float*)d_in[2];
    const float* Wv = (const float*)d_in[3];
    const float* Wp = (const float*)d_in[4];
    const float* bp = (const float*)d_in[5];
    float* out = (float*)d_out;

    (void)in_sizes; (void)n_in; (void)out_size;

    cudaFuncSetAttribute(attn3_kernel,
                         cudaFuncAttributeMaxDynamicSharedMemorySize,
                         ATT3_SMEM_BYTES);

    qkv_mma<<<dim3(9, 128), 256>>>(x, Wq, Wk, Wv);
    attn3_kernel<<<dim3(Bsz * Hn), 256, ATT3_SMEM_BYTES>>>();
    proj_mma<<<dim3(3, 128), 256>>>(Wp, bp, out);
}

// round 5
// speedup vs baseline: 3.5730x; 1.0804x over previous
#include <cuda_runtime.h>
#include <math.h>
#include <stdint.h>

#define Bsz  64
#define Tlen 256
#define Cdim 384
#define Hn   6
#define Dh   64
#define MTOT (Bsz*Tlen)
#define QKV_ELEMS (Bsz*Hn*Tlen*Dh)   // 6291456

__device__ float g_q[QKV_ELEMS];
__device__ float g_k[QKV_ELEMS];
__device__ float g_v[QKV_ELEMS];
__device__ float g_o[QKV_ELEMS];          // holds tf32 bit patterns after attn

__device__ uint32_t g_xt[MTOT * Cdim];    // X as tf32
__device__ uint32_t g_wb[3 * Cdim * 384]; // [mat][k][n], n = h*64+d, tf32
__device__ uint32_t g_wpt[Cdim * Cdim];   // [k][n] = Wp[n][k], tf32

// ---------------------------------------------------------------------------
// helpers
// ---------------------------------------------------------------------------
__device__ __forceinline__ uint32_t f2tf(float f) {
    uint32_t r;
    asm("cvt.rna.tf32.f32 %0, %1;" : "=r"(r) : "f"(f));
    return r;
}

__device__ __forceinline__ void mma_tf32(float d[4], const uint32_t a[4],
                                         const uint32_t b[2], const float c[4]) {
    asm volatile(
        "mma.sync.aligned.m16n8k8.row.col.f32.tf32.tf32.f32 "
        "{%0,%1,%2,%3}, {%4,%5,%6,%7}, {%8,%9}, {%10,%11,%12,%13};"
        : "=f"(d[0]), "=f"(d[1]), "=f"(d[2]), "=f"(d[3])
        : "r"(a[0]), "r"(a[1]), "r"(a[2]), "r"(a[3]),
          "r"(b[0]), "r"(b[1]),
          "f"(c[0]), "f"(c[1]), "f"(c[2]), "f"(c[3]));
}

__device__ __forceinline__ void cp16(void* dst, const void* src) {
    uint32_t s = (uint32_t)__cvta_generic_to_shared(dst);
    asm volatile("cp.async.ca.shared.global [%0], [%1], 16;" :: "r"(s), "l"(src));
}
#define CP_COMMIT() asm volatile("cp.async.commit_group;")
#define CP_WAIT1()  asm volatile("cp.async.wait_group 1;")
#define CP_WAIT0()  asm volatile("cp.async.wait_group 0;")

// ---------------------------------------------------------------------------
// Prologue: convert inputs/weights to tf32 once.
// ---------------------------------------------------------------------------
__global__ __launch_bounds__(256) void cvt_x_kernel(const float* __restrict__ X)
{
    int i = blockIdx.x * 256 + threadIdx.x;       // float4 index
    float4 v = ((const float4*)X)[i];
    uint4 u = make_uint4(f2tf(v.x), f2tf(v.y), f2tf(v.z), f2tf(v.w));
    ((uint4*)g_xt)[i] = u;
}

__global__ __launch_bounds__(256) void cvt_w_kernel(
    const float* __restrict__ Wq, const float* __restrict__ Wk,
    const float* __restrict__ Wv, const float* __restrict__ Wp)
{
    int i = blockIdx.x * 256 + threadIdx.x;
    const int NW = 3 * Cdim * 384;
    if (i < NW) {
        int mat = i / (Cdim * 384);
        int rem = i - mat * (Cdim * 384);
        int k = rem / 384, n = rem - (rem / 384) * 384;
        const float* W = (mat == 0) ? Wq : (mat == 1) ? Wk : Wv;
        int h = n >> 6, d = n & 63;
        g_wb[i] = f2tf(W[((size_t)h * Cdim + k) * Dh + d]);
    } else {
        int j = i - NW;                          // [0, 147456)
        int k = j / 384, n = j - k * 384;
        g_wpt[j] = f2tf(Wp[(size_t)n * Cdim + k]);
    }
}

// ---------------------------------------------------------------------------
// QKV projection: cp.async double-buffered tf32 MMA.
// CTA tile 128x128, warp tile 64x32, BK=32, NK=12.
// ---------------------------------------------------------------------------
#define ASTR 36
#define BSTR 136
#define A_WORDS (128 * ASTR)         // 4608
#define B_WORDS (32 * BSTR)          // 4352
#define GEMM_SMEM_BYTES ((2 * A_WORDS + 2 * B_WORDS) * 4)  // 71680

__global__ __launch_bounds__(256, 2) void qkv_mma(void)
{
    extern __shared__ uint32_t dynsm[];
    uint32_t* Asm = dynsm;
    uint32_t* Bsm = dynsm + 2 * A_WORDS;

    const int tid  = threadIdx.x;
    const int lane = tid & 31;
    const int warp = tid >> 5;
    const int gq   = lane >> 2;
    const int tg   = lane & 3;
    const int warpM = (warp >> 2) * 64;
    const int warpN = (warp & 3) * 32;

    const int nbase = blockIdx.x * 128;
    const int mat   = nbase / 384;
    const int nloc  = nbase - mat * 384;
    float* __restrict__ O = (mat == 0) ? g_q : (mat == 1) ? g_k : g_v;
    const int blockM = blockIdx.y * 128;

    const int arow = tid >> 3;            // 0..31
    const int akf  = (tid & 7) * 4;       // 0..28
    const int bk   = tid >> 5;            // 0..7
    const int bnf  = (tid & 31) * 4;      // 0..124

    const uint32_t* __restrict__ wbase = g_wb + (size_t)mat * Cdim * 384 + nloc;

    // stage tile kt into buffer buf
    auto stage = [&](int kt, int buf) {
        uint32_t* A = Asm + buf * A_WORDS;
        uint32_t* B = Bsm + buf * B_WORDS;
        #pragma unroll
        for (int p = 0; p < 4; p++) {
            int m = arow + 32 * p;
            cp16(&A[m * ASTR + akf], &g_xt[(size_t)(blockM + m) * Cdim + kt + akf]);
        }
        #pragma unroll
        for (int p = 0; p < 4; p++) {
            int k = bk + 8 * p;
            cp16(&B[k * BSTR + bnf], &wbase[(size_t)(kt + k) * 384 + bnf]);
        }
    };

    float acc[4][4][4];
    #pragma unroll
    for (int mt = 0; mt < 4; mt++)
        #pragma unroll
        for (int nt = 0; nt < 4; nt++)
            #pragma unroll
            for (int i = 0; i < 4; i++) acc[mt][nt][i] = 0.f;

    stage(0, 0);
    CP_COMMIT();

    const int NK = Cdim / 32;   // 12
    for (int it = 0; it < NK; it++) {
        if (it + 1 < NK) { stage(32 * (it + 1), (it + 1) & 1); CP_COMMIT(); CP_WAIT1(); }
        else            { CP_WAIT0(); }
        __syncthreads();

        const uint32_t* As = Asm + (it & 1) * A_WORDS;
        const uint32_t* Bs = Bsm + (it & 1) * B_WORDS;

        #pragma unroll
        for (int ks = 0; ks < 4; ks++) {
            const int k0 = ks * 8;
            uint32_t a[4][4];
            #pragma unroll
            for (int mt = 0; mt < 4; mt++) {
                int r0 = warpM + mt * 16 + gq;
                a[mt][0] = As[r0 * ASTR + k0 + tg];
                a[mt][1] = As[(r0 + 8) * ASTR + k0 + tg];
                a[mt][2] = As[r0 * ASTR + k0 + tg + 4];
                a[mt][3] = As[(r0 + 8) * ASTR + k0 + tg + 4];
            }
            uint32_t b[4][2];
            #pragma unroll
            for (int nt = 0; nt < 4; nt++) {
                int c0 = warpN + nt * 8 + gq;
                b[nt][0] = Bs[(k0 + tg) * BSTR + c0];
                b[nt][1] = Bs[(k0 + tg + 4) * BSTR + c0];
            }
            #pragma unroll
            for (int mt = 0; mt < 4; mt++)
                #pragma unroll
                for (int nt = 0; nt < 4; nt++)
                    mma_tf32(acc[mt][nt], a[mt], b[nt], acc[mt][nt]);
        }
        __syncthreads();
    }

    // epilogue -> [B,H,T,D]; C rows gq / gq+8
    #pragma unroll
    for (int mt = 0; mt < 4; mt++) {
        #pragma unroll
        for (int nt = 0; nt < 4; nt++) {
            int cloc = nloc + warpN + nt * 8 + 2 * tg;
            int h = cloc >> 6, d = cloc & 63;
            int r = blockM + warpM + mt * 16 + gq;
            int bb = r >> 8, t = r & 255;
            float2 v0 = make_float2(acc[mt][nt][0], acc[mt][nt][1]);
            *(float2*)&O[(((size_t)bb * Hn + h) * Tlen + t) * Dh + d] = v0;
            float2 v1 = make_float2(acc[mt][nt][2], acc[mt][nt][3]);
            *(float2*)&O[(((size_t)bb * Hn + h) * Tlen + (t + 8)) * Dh + d] = v1;
        }
    }
}

// ---------------------------------------------------------------------------
// Output projection: cp.async double-buffered tf32 MMA.
// A = g_o (already tf32 bits), B = g_wpt.
// ---------------------------------------------------------------------------
__global__ __launch_bounds__(256, 2) void proj_mma(
    const float* __restrict__ bp,
    float* __restrict__ out)
{
    extern __shared__ uint32_t dynsm[];
    uint32_t* Asm = dynsm;
    uint32_t* Bsm = dynsm + 2 * A_WORDS;

    const int tid  = threadIdx.x;
    const int lane = tid & 31;
    const int warp = tid >> 5;
    const int gq   = lane >> 2;
    const int tg   = lane & 3;
    const int warpM = (warp >> 2) * 64;
    const int warpN = (warp & 3) * 32;

    const int blockN = blockIdx.x * 128;
    const int blockM = blockIdx.y * 128;

    const int arow = tid >> 3;
    const int akf  = (tid & 7) * 4;
    const int bk   = tid >> 5;
    const int bnf  = (tid & 31) * 4;

    auto stage = [&](int kt, int buf) {
        uint32_t* A = Asm + buf * A_WORDS;
        uint32_t* B = Bsm + buf * B_WORDS;
        #pragma unroll
        for (int p = 0; p < 4; p++) {
            int m = arow + 32 * p;
            int mg = blockM + m;
            int kg = kt + akf;
            size_t addr = (((size_t)(mg >> 8)) * Hn + (kg >> 6)) * (Tlen * Dh)
                        + (size_t)(mg & 255) * Dh + (kg & 63);
            cp16(&A[m * ASTR + akf], &g_o[addr]);
        }
        #pragma unroll
        for (int p = 0; p < 4; p++) {
            int k = bk + 8 * p;
            cp16(&B[k * BSTR + bnf], &g_wpt[(size_t)(kt + k) * 384 + blockN + bnf]);
        }
    };

    float acc[4][4][4];
    #pragma unroll
    for (int mt = 0; mt < 4; mt++)
        #pragma unroll
        for (int nt = 0; nt < 4; nt++)
            #pragma unroll
            for (int i = 0; i < 4; i++) acc[mt][nt][i] = 0.f;

    stage(0, 0);
    CP_COMMIT();

    const int NK = Cdim / 32;
    for (int it = 0; it < NK; it++) {
        if (it + 1 < NK) { stage(32 * (it + 1), (it + 1) & 1); CP_COMMIT(); CP_WAIT1(); }
        else            { CP_WAIT0(); }
        __syncthreads();

        const uint32_t* As = Asm + (it & 1) * A_WORDS;
        const uint32_t* Bs = Bsm + (it & 1) * B_WORDS;

        #pragma unroll
        for (int ks = 0; ks < 4; ks++) {
            const int k0 = ks * 8;
            uint32_t a[4][4];
            #pragma unroll
            for (int mt = 0; mt < 4; mt++) {
                int r0 = warpM + mt * 16 + gq;
                a[mt][0] = As[r0 * ASTR + k0 + tg];
                a[mt][1] = As[(r0 + 8) * ASTR + k0 + tg];
                a[mt][2] = As[r0 * ASTR + k0 + tg + 4];
                a[mt][3] = As[(r0 + 8) * ASTR + k0 + tg + 4];
            }
            uint32_t b[4][2];
            #pragma unroll
            for (int nt = 0; nt < 4; nt++) {
                int c0 = warpN + nt * 8 + gq;
                b[nt][0] = Bs[(k0 + tg) * BSTR + c0];
                b[nt][1] = Bs[(k0 + tg + 4) * BSTR + c0];
            }
            #pragma unroll
            for (int mt = 0; mt < 4; mt++)
                #pragma unroll
                for (int nt = 0; nt < 4; nt++)
                    mma_tf32(acc[mt][nt], a[mt], b[nt], acc[mt][nt]);
        }
        __syncthreads();
    }

    #pragma unroll
    for (int mt = 0; mt < 4; mt++) {
        #pragma unroll
        for (int nt = 0; nt < 4; nt++) {
            int n = blockN + warpN + nt * 8 + 2 * tg;
            float b0 = bp[n], b1 = bp[n + 1];
            int r = blockM + warpM + mt * 16 + gq;
            float2 v0 = make_float2(acc[mt][nt][0] + b0, acc[mt][nt][1] + b1);
            *(float2*)&out[(size_t)r * Cdim + n] = v0;
            float2 v1 = make_float2(acc[mt][nt][2] + b0, acc[mt][nt][3] + b1);
            *(float2*)&out[(size_t)(r + 8) * Cdim + n] = v1;
        }
    }
}

// ---------------------------------------------------------------------------
// Flash-style tensor-core attention (round 4) — epilogue now writes tf32 bits.
// ---------------------------------------------------------------------------
#define KTS 264
#define VSS 72
#define QSS 68
#define PSS 68
#define OFF_KT 0
#define OFF_VS (OFF_KT + 64 * KTS)
#define OFF_QS (OFF_VS + 256 * VSS)
#define OFF_PS (OFF_QS + 128 * QSS)
#define ATT3_SMEM_WORDS (OFF_PS + 128 * PSS)
#define ATT3_SMEM_BYTES (ATT3_SMEM_WORDS * 4)   // 210944

__global__ __launch_bounds__(256) void attn3_kernel()
{
    extern __shared__ __align__(16) uint32_t smu[];
    uint32_t* Kt = smu + OFF_KT;
    uint32_t* Vs = smu + OFF_VS;
    uint32_t* Qs = smu + OFF_QS;
    uint32_t* Ps = smu + OFF_PS;

    const int bh = blockIdx.x;
    const size_t base = (size_t)bh * (Tlen * Dh);
    const int tid  = threadIdx.x;
    const int lane = tid & 31;
    const int warp = tid >> 5;
    const int gq   = lane >> 2;
    const int tg   = lane & 3;
    const int wrow = warp * 16;

    {
        const int s0  = tid & 31;
        const int d4b = tid >> 5;
        #pragma unroll
        for (int it = 0; it < 16; it++) {
            int d4 = d4b + 8 * (it & 1);
            int s  = s0 + 32 * (it >> 1);
            float4 v = *(const float4*)&g_k[base + (size_t)s * Dh + d4 * 4];
            Kt[(4 * d4 + 0) * KTS + s] = f2tf(v.x);
            Kt[(4 * d4 + 1) * KTS + s] = f2tf(v.y);
            Kt[(4 * d4 + 2) * KTS + s] = f2tf(v.z);
            Kt[(4 * d4 + 3) * KTS + s] = f2tf(v.w);
        }
    }
    #pragma unroll
    for (int it = 0; it < 16; it++) {
        int idx = tid + 256 * it;
        int s = idx >> 4, d4 = idx & 15;
        float4 v = *(const float4*)&g_v[base + (size_t)idx * 4];
        uint4 u = make_uint4(f2tf(v.x), f2tf(v.y), f2tf(v.z), f2tf(v.w));
        *(uint4*)&Vs[s * VSS + 4 * d4] = u;
    }

    const float scale = 0.125f;

    for (int qi = 0; qi < 2; qi++) {
        __syncthreads();
        #pragma unroll
        for (int it = 0; it < 8; it++) {
            int idx = tid + 256 * it;
            int m = idx >> 4, d4 = idx & 15;
            float4 v = *(const float4*)&g_q[base + (size_t)(qi * 128 + m) * Dh + 4 * d4];
            uint4 u = make_uint4(f2tf(v.x), f2tf(v.y), f2tf(v.z), f2tf(v.w));
            *(uint4*)&Qs[m * QSS + 4 * d4] = u;
        }
        __syncthreads();

        const int row0 = qi * 128 + wrow + gq;
        const int row1 = row0 + 8;
        const int rowmax_warp = qi * 128 + wrow + 15;

        float m0r = -INFINITY, m1r = -INFINITY;
        float l0 = 0.f, l1 = 0.f;
        float o[8][4];
        #pragma unroll
        for (int nt = 0; nt < 8; nt++)
            #pragma unroll
            for (int c = 0; c < 4; c++) o[nt][c] = 0.f;

        const int nblocks = 2 * qi + 2;
        for (int sb = 0; sb < nblocks; sb++) {
            if (sb * 64 > rowmax_warp) continue;

            float sacc[8][4];
            #pragma unroll
            for (int nt = 0; nt < 8; nt++)
                #pragma unroll
                for (int c = 0; c < 4; c++) sacc[nt][c] = 0.f;

            #pragma unroll
            for (int ks = 0; ks < 8; ks++) {
                const int kk = ks * 8;
                uint32_t a[4];
                a[0] = Qs[(wrow + gq) * QSS + kk + tg];
                a[1] = Qs[(wrow + gq + 8) * QSS + kk + tg];
                a[2] = Qs[(wrow + gq) * QSS + kk + tg + 4];
                a[3] = Qs[(wrow + gq + 8) * QSS + kk + tg + 4];
                #pragma unroll
                for (int nt = 0; nt < 8; nt++) {
                    uint32_t b[2];
                    const int cc = sb * 64 + nt * 8 + gq;
                    b[0] = Kt[(kk + tg) * KTS + cc];
                    b[1] = Kt[(kk + tg + 4) * KTS + cc];
                    mma_tf32(sacc[nt], a, b, sacc[nt]);
                }
            }

            float bm0 = -INFINITY, bm1 = -INFINITY;
            #pragma unroll
            for (int nt = 0; nt < 8; nt++) {
                const int c0 = sb * 64 + nt * 8 + 2 * tg;
                float v00 = (c0     <= row0) ? sacc[nt][0] * scale : -INFINITY;
                float v01 = (c0 + 1 <= row0) ? sacc[nt][1] * scale : -INFINITY;
                float v10 = (c0     <= row1) ? sacc[nt][2] * scale : -INFINITY;
                float v11 = (c0 + 1 <= row1) ? sacc[nt][3] * scale : -INFINITY;
                sacc[nt][0] = v00; sacc[nt][1] = v01;
                sacc[nt][2] = v10; sacc[nt][3] = v11;
                bm0 = fmaxf(bm0, fmaxf(v00, v01));
                bm1 = fmaxf(bm1, fmaxf(v10, v11));
            }
            bm0 = fmaxf(bm0, __shfl_xor_sync(0xffffffffu, bm0, 1));
            bm0 = fmaxf(bm0, __shfl_xor_sync(0xffffffffu, bm0, 2));
            bm1 = fmaxf(bm1, __shfl_xor_sync(0xffffffffu, bm1, 1));
            bm1 = fmaxf(bm1, __shfl_xor_sync(0xffffffffu, bm1, 2));

            const float mn0 = fmaxf(m0r, bm0);
            const float mn1 = fmaxf(m1r, bm1);
            const float cor0 = __expf(m0r - mn0);
            const float cor1 = __expf(m1r - mn1);
            m0r = mn0; m1r = mn1;

            float rs0 = 0.f, rs1 = 0.f;
            #pragma unroll
            for (int nt = 0; nt < 8; nt++) {
                float p00 = __expf(sacc[nt][0] - mn0);
                float p01 = __expf(sacc[nt][1] - mn0);
                float p10 = __expf(sacc[nt][2] - mn1);
                float p11 = __expf(sacc[nt][3] - mn1);
                rs0 += p00 + p01;
                rs1 += p10 + p11;
                uint2 u0 = make_uint2(f2tf(p00), f2tf(p01));
                *(uint2*)&Ps[(wrow + gq) * PSS + nt * 8 + 2 * tg] = u0;
                uint2 u1 = make_uint2(f2tf(p10), f2tf(p11));
                *(uint2*)&Ps[(wrow + gq + 8) * PSS + nt * 8 + 2 * tg] = u1;
            }
            rs0 += __shfl_xor_sync(0xffffffffu, rs0, 1);
            rs0 += __shfl_xor_sync(0xffffffffu, rs0, 2);
            rs1 += __shfl_xor_sync(0xffffffffu, rs1, 1);
            rs1 += __shfl_xor_sync(0xffffffffu, rs1, 2);
            l0 = l0 * cor0 + rs0;
            l1 = l1 * cor1 + rs1;

            #pragma unroll
            for (int nt = 0; nt < 8; nt++) {
                o[nt][0] *= cor0; o[nt][1] *= cor0;
                o[nt][2] *= cor1; o[nt][3] *= cor1;
            }
            __syncwarp();

            #pragma unroll
            for (int ks = 0; ks < 8; ks++) {
                const int kk = ks * 8;
                uint32_t a[4];
                a[0] = Ps[(wrow + gq) * PSS + kk + tg];
                a[1] = Ps[(wrow + gq + 8) * PSS + kk + tg];
                a[2] = Ps[(wrow + gq) * PSS + kk + tg + 4];
                a[3] = Ps[(wrow + gq + 8) * PSS + kk + tg + 4];
                #pragma unroll
                for (int nt = 0; nt < 8; nt++) {
                    uint32_t b[2];
                    b[0] = Vs[(sb * 64 + kk + tg) * VSS + nt * 8 + gq];
                    b[1] = Vs[(sb * 64 + kk + tg + 4) * VSS + nt * 8 + gq];
                    mma_tf32(o[nt], a, b, o[nt]);
                }
            }
            __syncwarp();
        }

        // finalize: write tf32 bit patterns (consumed raw by proj_mma cp.async)
        const float inv0 = 1.0f / l0;
        const float inv1 = 1.0f / l1;
        #pragma unroll
        for (int nt = 0; nt < 8; nt++) {
            const int col = nt * 8 + 2 * tg;
            float2 v0 = make_float2(__uint_as_float(f2tf(o[nt][0] * inv0)),
                                    __uint_as_float(f2tf(o[nt][1] * inv0)));
            *(float2*)&g_o[base + (size_t)row0 * Dh + col] = v0;
            float2 v1 = make_float2(__uint_as_float(f2tf(o[nt][2] * inv1)),
                                    __uint_as_float(f2tf(o[nt][3] * inv1)));
            *(float2*)&g_o[base + (size_t)row1 * Dh + col] = v1;
        }
    }
}

// ---------------------------------------------------------------------------
extern "C" void kernel_launch(void* const* d_in, const int* in_sizes, int n_in,
                              void* d_out, int out_size)
{
    const float* x  = (const float*)d_in[0];
    const float* Wq = (const float*)d_in[1];
    const float* Wk = (const float*)d_in[2];
    const float* Wv = (const float*)d_in[3];
    const float* Wp = (const float*)d_in[4];
    const float* bp = (const float*)d_in[5];
    float* out = (float*)d_out;

    (void)in_sizes; (void)n_in; (void)out_size;

    cudaFuncSetAttribute(qkv_mma,
                         cudaFuncAttributeMaxDynamicSharedMemorySize, GEMM_SMEM_BYTES);
    cudaFuncSetAttribute(proj_mma,
                         cudaFuncAttributeMaxDynamicSharedMemorySize, GEMM_SMEM_BYTES);
    cudaFuncSetAttribute(attn3_kernel,
                         cudaFuncAttributeMaxDynamicSharedMemorySize, ATT3_SMEM_BYTES);

    cvt_x_kernel<<<(MTOT * Cdim / 4) / 256, 256>>>(x);
    cvt_w_kernel<<<(4 * Cdim * 384) / 256, 256>>>(Wq, Wk, Wv, Wp);
    qkv_mma<<<dim3(9, 128), 256, GEMM_SMEM_BYTES>>>();
    attn3_kernel<<<dim3(Bsz * Hn), 256, ATT3_SMEM_BYTES>>>();
    proj_mma<<<dim3(3, 128), 256, GEMM_SMEM_BYTES>>>(bp, out);
}

// round 7
// speedup vs baseline: 3.7048x; 1.0369x over previous
#include <cuda_runtime.h>
#include <math.h>
#include <stdint.h>

#define Bsz  64
#define Tlen 256
#define Cdim 384
#define Hn   6
#define Dh   64
#define MTOT (Bsz*Tlen)
#define QKV_ELEMS (Bsz*Hn*Tlen*Dh)   // 6291456

__device__ float g_q[QKV_ELEMS];
__device__ float g_k[QKV_ELEMS];
__device__ float g_v[QKV_ELEMS];
__device__ float g_o[QKV_ELEMS];          // tf32 bit patterns after attn

__device__ uint32_t g_xt[MTOT * Cdim];    // X as tf32
__device__ uint32_t g_wb[3 * Cdim * 384]; // [mat][k][n], n = h*64+d, tf32
__device__ uint32_t g_wpt[Cdim * Cdim];   // [k][n] = Wp[n][k], tf32

// ---------------------------------------------------------------------------
// helpers
// ---------------------------------------------------------------------------
__device__ __forceinline__ uint32_t f2tf(float f) {
    uint32_t r;
    asm("cvt.rna.tf32.f32 %0, %1;" : "=r"(r) : "f"(f));
    return r;
}

__device__ __forceinline__ void mma_tf32(float d[4], const uint32_t a[4],
                                         const uint32_t b[2], const float c[4]) {
    asm volatile(
        "mma.sync.aligned.m16n8k8.row.col.f32.tf32.tf32.f32 "
        "{%0,%1,%2,%3}, {%4,%5,%6,%7}, {%8,%9}, {%10,%11,%12,%13};"
        : "=f"(d[0]), "=f"(d[1]), "=f"(d[2]), "=f"(d[3])
        : "r"(a[0]), "r"(a[1]), "r"(a[2]), "r"(a[3]),
          "r"(b[0]), "r"(b[1]),
          "f"(c[0]), "f"(c[1]), "f"(c[2]), "f"(c[3]));
}

__device__ __forceinline__ void cp16(void* dst, const void* src) {
    uint32_t s = (uint32_t)__cvta_generic_to_shared(dst);
    asm volatile("cp.async.ca.shared.global [%0], [%1], 16;" :: "r"(s), "l"(src));
}
#define CP_COMMIT() asm volatile("cp.async.commit_group;")
#define CP_WAIT1()  asm volatile("cp.async.wait_group 1;")
#define CP_WAIT0()  asm volatile("cp.async.wait_group 0;")

// ---------------------------------------------------------------------------
// Prologue: convert inputs/weights to tf32 once.
// ---------------------------------------------------------------------------
__global__ __launch_bounds__(256) void cvt_x_kernel(const float* __restrict__ X)
{
    int i = blockIdx.x * 256 + threadIdx.x;       // float4 index
    float4 v = ((const float4*)X)[i];
    uint4 u = make_uint4(f2tf(v.x), f2tf(v.y), f2tf(v.z), f2tf(v.w));
    ((uint4*)g_xt)[i] = u;
}

__global__ __launch_bounds__(256) void cvt_w_kernel(
    const float* __restrict__ Wq, const float* __restrict__ Wk,
    const float* __restrict__ Wv, const float* __restrict__ Wp)
{
    int i = blockIdx.x * 256 + threadIdx.x;
    const int NW = 3 * Cdim * 384;
    if (i < NW) {
        int mat = i / (Cdim * 384);
        int rem = i - mat * (Cdim * 384);
        int k = rem / 384, n = rem - (rem / 384) * 384;
        const float* W = (mat == 0) ? Wq : (mat == 1) ? Wk : Wv;
        int h = n >> 6, d = n & 63;
        g_wb[i] = f2tf(W[((size_t)h * Cdim + k) * Dh + d]);
    } else {
        int j = i - NW;                          // [0, 147456)
        int k = j / 384, n = j - k * 384;
        g_wpt[j] = f2tf(Wp[(size_t)n * Cdim + k]);
    }
}

// ---------------------------------------------------------------------------
// QKV projection: cp.async double-buffered tf32 MMA (round-5, known good).
// ---------------------------------------------------------------------------
#define ASTR 36
#define BSTR 136
#define A_WORDS (128 * ASTR)         // 4608
#define B_WORDS (32 * BSTR)          // 4352
#define GEMM_SMEM_BYTES ((2 * A_WORDS + 2 * B_WORDS) * 4)  // 71680

__global__ __launch_bounds__(256, 2) void qkv_mma(void)
{
    extern __shared__ uint32_t dynsm[];
    uint32_t* Asm = dynsm;
    uint32_t* Bsm = dynsm + 2 * A_WORDS;

    const int tid  = threadIdx.x;
    const int lane = tid & 31;
    const int warp = tid >> 5;
    const int gq   = lane >> 2;
    const int tg   = lane & 3;
    const int warpM = (warp >> 2) * 64;
    const int warpN = (warp & 3) * 32;

    const int nbase = blockIdx.x * 128;
    const int mat   = nbase / 384;
    const int nloc  = nbase - mat * 384;
    float* __restrict__ O = (mat == 0) ? g_q : (mat == 1) ? g_k : g_v;
    const int blockM = blockIdx.y * 128;

    const int arow = tid >> 3;            // 0..31
    const int akf  = (tid & 7) * 4;       // 0..28
    const int bk   = tid >> 5;            // 0..7
    const int bnf  = (tid & 31) * 4;      // 0..124

    const uint32_t* __restrict__ wbase = g_wb + (size_t)mat * Cdim * 384 + nloc;

    auto stage = [&](int kt, int buf) {
        uint32_t* A = Asm + buf * A_WORDS;
        uint32_t* B = Bsm + buf * B_WORDS;
        #pragma unroll
        for (int p = 0; p < 4; p++) {
            int m = arow + 32 * p;
            cp16(&A[m * ASTR + akf], &g_xt[(size_t)(blockM + m) * Cdim + kt + akf]);
        }
        #pragma unroll
        for (int p = 0; p < 4; p++) {
            int k = bk + 8 * p;
            cp16(&B[k * BSTR + bnf], &wbase[(size_t)(kt + k) * 384 + bnf]);
        }
    };

    float acc[4][4][4];
    #pragma unroll
    for (int mt = 0; mt < 4; mt++)
        #pragma unroll
        for (int nt = 0; nt < 4; nt++)
            #pragma unroll
            for (int i = 0; i < 4; i++) acc[mt][nt][i] = 0.f;

    stage(0, 0);
    CP_COMMIT();

    const int NK = Cdim / 32;   // 12
    for (int it = 0; it < NK; it++) {
        if (it + 1 < NK) { stage(32 * (it + 1), (it + 1) & 1); CP_COMMIT(); CP_WAIT1(); }
        else            { CP_WAIT0(); }
        __syncthreads();

        const uint32_t* As = Asm + (it & 1) * A_WORDS;
        const uint32_t* Bs = Bsm + (it & 1) * B_WORDS;

        #pragma unroll
        for (int ks = 0; ks < 4; ks++) {
            const int k0 = ks * 8;
            uint32_t a[4][4];
            #pragma unroll
            for (int mt = 0; mt < 4; mt++) {
                int r0 = warpM + mt * 16 + gq;
                a[mt][0] = As[r0 * ASTR + k0 + tg];
                a[mt][1] = As[(r0 + 8) * ASTR + k0 + tg];
                a[mt][2] = As[r0 * ASTR + k0 + tg + 4];
                a[mt][3] = As[(r0 + 8) * ASTR + k0 + tg + 4];
            }
            uint32_t b[4][2];
            #pragma unroll
            for (int nt = 0; nt < 4; nt++) {
                int c0 = warpN + nt * 8 + gq;
                b[nt][0] = Bs[(k0 + tg) * BSTR + c0];
                b[nt][1] = Bs[(k0 + tg + 4) * BSTR + c0];
            }
            #pragma unroll
            for (int mt = 0; mt < 4; mt++)
                #pragma unroll
                for (int nt = 0; nt < 4; nt++)
                    mma_tf32(acc[mt][nt], a[mt], b[nt], acc[mt][nt]);
        }
        __syncthreads();
    }

    #pragma unroll
    for (int mt = 0; mt < 4; mt++) {
        #pragma unroll
        for (int nt = 0; nt < 4; nt++) {
            int cloc = nloc + warpN + nt * 8 + 2 * tg;
            int h = cloc >> 6, d = cloc & 63;
            int r = blockM + warpM + mt * 16 + gq;
            int bb = r >> 8, t = r & 255;
            float2 v0 = make_float2(acc[mt][nt][0], acc[mt][nt][1]);
            *(float2*)&O[(((size_t)bb * Hn + h) * Tlen + t) * Dh + d] = v0;
            float2 v1 = make_float2(acc[mt][nt][2], acc[mt][nt][3]);
            *(float2*)&O[(((size_t)bb * Hn + h) * Tlen + (t + 8)) * Dh + d] = v1;
        }
    }
}

// ---------------------------------------------------------------------------
// Output projection: cp.async double-buffered tf32 MMA (round-5, known good).
// ---------------------------------------------------------------------------
__global__ __launch_bounds__(256, 2) void proj_mma(
    const float* __restrict__ bp,
    float* __restrict__ out)
{
    extern __shared__ uint32_t dynsm[];
    uint32_t* Asm = dynsm;
    uint32_t* Bsm = dynsm + 2 * A_WORDS;

    const int tid  = threadIdx.x;
    const int lane = tid & 31;
    const int warp = tid >> 5;
    const int gq   = lane >> 2;
    const int tg   = lane & 3;
    const int warpM = (warp >> 2) * 64;
    const int warpN = (warp & 3) * 32;

    const int blockN = blockIdx.x * 128;
    const int blockM = blockIdx.y * 128;

    const int arow = tid >> 3;
    const int akf  = (tid & 7) * 4;
    const int bk   = tid >> 5;
    const int bnf  = (tid & 31) * 4;

    auto stage = [&](int kt, int buf) {
        uint32_t* A = Asm + buf * A_WORDS;
        uint32_t* B = Bsm + buf * B_WORDS;
        #pragma unroll
        for (int p = 0; p < 4; p++) {
            int m = arow + 32 * p;
            int mg = blockM + m;
            int kg = kt + akf;
            size_t addr = (((size_t)(mg >> 8)) * Hn + (kg >> 6)) * (Tlen * Dh)
                        + (size_t)(mg & 255) * Dh + (kg & 63);
            cp16(&A[m * ASTR + akf], &g_o[addr]);
        }
        #pragma unroll
        for (int p = 0; p < 4; p++) {
            int k = bk + 8 * p;
            cp16(&B[k * BSTR + bnf], &g_wpt[(size_t)(kt + k) * 384 + blockN + bnf]);
        }
    };

    float acc[4][4][4];
    #pragma unroll
    for (int mt = 0; mt < 4; mt++)
        #pragma unroll
        for (int nt = 0; nt < 4; nt++)
            #pragma unroll
            for (int i = 0; i < 4; i++) acc[mt][nt][i] = 0.f;

    stage(0, 0);
    CP_COMMIT();

    const int NK = Cdim / 32;
    for (int it = 0; it < NK; it++) {
        if (it + 1 < NK) { stage(32 * (it + 1), (it + 1) & 1); CP_COMMIT(); CP_WAIT1(); }
        else            { CP_WAIT0(); }
        __syncthreads();

        const uint32_t* As = Asm + (it & 1) * A_WORDS;
        const uint32_t* Bs = Bsm + (it & 1) * B_WORDS;

        #pragma unroll
        for (int ks = 0; ks < 4; ks++) {
            const int k0 = ks * 8;
            uint32_t a[4][4];
            #pragma unroll
            for (int mt = 0; mt < 4; mt++) {
                int r0 = warpM + mt * 16 + gq;
                a[mt][0] = As[r0 * ASTR + k0 + tg];
                a[mt][1] = As[(r0 + 8) * ASTR + k0 + tg];
                a[mt][2] = As[r0 * ASTR + k0 + tg + 4];
                a[mt][3] = As[(r0 + 8) * ASTR + k0 + tg + 4];
            }
            uint32_t b[4][2];
            #pragma unroll
            for (int nt = 0; nt < 4; nt++) {
                int c0 = warpN + nt * 8 + gq;
                b[nt][0] = Bs[(k0 + tg) * BSTR + c0];
                b[nt][1] = Bs[(k0 + tg + 4) * BSTR + c0];
            }
            #pragma unroll
            for (int mt = 0; mt < 4; mt++)
                #pragma unroll
                for (int nt = 0; nt < 4; nt++)
                    mma_tf32(acc[mt][nt], a[mt], b[nt], acc[mt][nt]);
        }
        __syncthreads();
    }

    #pragma unroll
    for (int mt = 0; mt < 4; mt++) {
        #pragma unroll
        for (int nt = 0; nt < 4; nt++) {
            int n = blockN + warpN + nt * 8 + 2 * tg;
            float b0 = bp[n], b1 = bp[n + 1];
            int r = blockM + warpM + mt * 16 + gq;
            float2 v0 = make_float2(acc[mt][nt][0] + b0, acc[mt][nt][1] + b1);
            *(float2*)&out[(size_t)r * Cdim + n] = v0;
            float2 v1 = make_float2(acc[mt][nt][2] + b0, acc[mt][nt][3] + b1);
            *(float2*)&out[(size_t)(r + 8) * Cdim + n] = v1;
        }
    }
}

// ---------------------------------------------------------------------------
// attn4: 16 warps per CTA, warp w owns rows [16w, 16w+16) of full T=256.
// Q fragments in registers (loaded once from g_q). No Qs buffer, no
// block-level syncs after staging. Causal: warp w runs wrow/64+1 s-blocks.
// ---------------------------------------------------------------------------
#define KTS 264
#define VSS 72
#define PSS 68
#define A4_KT 0
#define A4_VS (A4_KT + 64 * KTS)                // 16896
#define A4_PS (A4_VS + 256 * VSS)               // 35328
#define ATT4_SMEM_WORDS (A4_PS + 256 * PSS)     // 52736
#define ATT4_SMEM_BYTES (ATT4_SMEM_WORDS * 4)   // 210944

__global__ __launch_bounds__(512) void attn4_kernel()
{
    extern __shared__ __align__(16) uint32_t smu[];
    uint32_t* Kt = smu + A4_KT;
    uint32_t* Vs = smu + A4_VS;
    uint32_t* Ps = smu + A4_PS;

    const int bh = blockIdx.x;
    const size_t base = (size_t)bh * (Tlen * Dh);
    const int tid  = threadIdx.x;
    const int lane = tid & 31;
    const int warp = tid >> 5;           // 0..15
    const int gq   = lane >> 2;
    const int tg   = lane & 3;
    const int wrow = warp * 16;

    // --- Stage K transposed: Kt[d][s] ---
    {
        const int s0  = tid & 31;
        const int d4b = tid >> 5;        // 0..15
        #pragma unroll
        for (int it = 0; it < 8; it++) {
            int s  = s0 + 32 * it;
            float4 v = *(const float4*)&g_k[base + (size_t)s * Dh + d4b * 4];
            Kt[(4 * d4b + 0) * KTS + s] = f2tf(v.x);
            Kt[(4 * d4b + 1) * KTS + s] = f2tf(v.y);
            Kt[(4 * d4b + 2) * KTS + s] = f2tf(v.z);
            Kt[(4 * d4b + 3) * KTS + s] = f2tf(v.w);
        }
    }
    // --- Stage V natural: Vs[s][d] ---
    #pragma unroll
    for (int it = 0; it < 8; it++) {
        int idx = tid + 512 * it;        // float4 index, [0,4096)
        int s = idx >> 4, d4 = idx & 15;
        float4 v = *(const float4*)&g_v[base + (size_t)idx * 4];
        uint4 u = make_uint4(f2tf(v.x), f2tf(v.y), f2tf(v.z), f2tf(v.w));
        *(uint4*)&Vs[s * VSS + 4 * d4] = u;
    }

    // --- Q fragments in registers (reused across all s-blocks) ---
    const int row0 = wrow + gq;
    const int row1 = row0 + 8;
    uint32_t qfr[8][4];
    {
        const float* q0 = &g_q[base + (size_t)row0 * Dh];
        const float* q1 = &g_q[base + (size_t)row1 * Dh];
        #pragma unroll
        for (int ks = 0; ks < 8; ks++) {
            const int kk = ks * 8;
            qfr[ks][0] = f2tf(q0[kk + tg]);
            qfr[ks][1] = f2tf(q1[kk + tg]);
            qfr[ks][2] = f2tf(q0[kk + tg + 4]);
            qfr[ks][3] = f2tf(q1[kk + tg + 4]);
        }
    }
    __syncthreads();

    const float scale = 0.125f;

    float m0r = -INFINITY, m1r = -INFINITY;
    float l0 = 0.f, l1 = 0.f;
    float o[8][4];
    #pragma unroll
    for (int nt = 0; nt < 8; nt++)
        #pragma unroll
        for (int c = 0; c < 4; c++) o[nt][c] = 0.f;

    const int nblocks = (wrow >> 6) + 1;       // 1..4, warp-uniform
    for (int sb = 0; sb < nblocks; sb++) {

        // ---- S = Q K^T (16 rows x 64 cols) ----
        float sacc[8][4];
        #pragma unroll
        for (int nt = 0; nt < 8; nt++)
            #pragma unroll
            for (int c = 0; c < 4; c++) sacc[nt][c] = 0.f;

        #pragma unroll
        for (int ks = 0; ks < 8; ks++) {
            const int kk = ks * 8;
            #pragma unroll
            for (int nt = 0; nt < 8; nt++) {
                uint32_t b[2];
                const int cc = sb * 64 + nt * 8 + gq;
                b[0] = Kt[(kk + tg) * KTS + cc];
                b[1] = Kt[(kk + tg + 4) * KTS + cc];
                mma_tf32(sacc[nt], qfr[ks], b, sacc[nt]);
            }
        }

        // ---- mask + online softmax ----
        float bm0 = -INFINITY, bm1 = -INFINITY;
        #pragma unroll
        for (int nt = 0; nt < 8; nt++) {
            const int c0 = sb * 64 + nt * 8 + 2 * tg;
            float v00 = (c0     <= row0) ? sacc[nt][0] * scale : -INFINITY;
            float v01 = (c0 + 1 <= row0) ? sacc[nt][1] * scale : -INFINITY;
            float v10 = (c0     <= row1) ? sacc[nt][2] * scale : -INFINITY;
            float v11 = (c0 + 1 <= row1) ? sacc[nt][3] * scale : -INFINITY;
            sacc[nt][0] = v00; sacc[nt][1] = v01;
            sacc[nt][2] = v10; sacc[nt][3] = v11;
            bm0 = fmaxf(bm0, fmaxf(v00, v01));
            bm1 = fmaxf(bm1, fmaxf(v10, v11));
        }
        bm0 = fmaxf(bm0, __shfl_xor_sync(0xffffffffu, bm0, 1));
        bm0 = fmaxf(bm0, __shfl_xor_sync(0xffffffffu, bm0, 2));
        bm1 = fmaxf(bm1, __shfl_xor_sync(0xffffffffu, bm1, 1));
        bm1 = fmaxf(bm1, __shfl_xor_sync(0xffffffffu, bm1, 2));

        const float mn0 = fmaxf(m0r, bm0);
        const float mn1 = fmaxf(m1r, bm1);
        const float cor0 = __expf(m0r - mn0);
        const float cor1 = __expf(m1r - mn1);
        m0r = mn0; m1r = mn1;

        float rs0 = 0.f, rs1 = 0.f;
        #pragma unroll
        for (int nt = 0; nt < 8; nt++) {
            float p00 = __expf(sacc[nt][0] - mn0);
            float p01 = __expf(sacc[nt][1] - mn0);
            float p10 = __expf(sacc[nt][2] - mn1);
            float p11 = __expf(sacc[nt][3] - mn1);
            rs0 += p00 + p01;
            rs1 += p10 + p11;
            uint2 u0 = make_uint2(f2tf(p00), f2tf(p01));
            *(uint2*)&Ps[(wrow + gq) * PSS + nt * 8 + 2 * tg] = u0;
            uint2 u1 = make_uint2(f2tf(p10), f2tf(p11));
            *(uint2*)&Ps[(wrow + gq + 8) * PSS + nt * 8 + 2 * tg] = u1;
        }
        rs0 += __shfl_xor_sync(0xffffffffu, rs0, 1);
        rs0 += __shfl_xor_sync(0xffffffffu, rs0, 2);
        rs1 += __shfl_xor_sync(0xffffffffu, rs1, 1);
        rs1 += __shfl_xor_sync(0xffffffffu, rs1, 2);
        l0 = l0 * cor0 + rs0;
        l1 = l1 * cor1 + rs1;

        #pragma unroll
        for (int nt = 0; nt < 8; nt++) {
            o[nt][0] *= cor0; o[nt][1] *= cor0;
            o[nt][2] *= cor1; o[nt][3] *= cor1;
        }
        __syncwarp();

        // ---- O += P V ----
        #pragma unroll
        for (int ks = 0; ks < 8; ks++) {
            const int kk = ks * 8;
            uint32_t a[4];
            a[0] = Ps[(wrow + gq) * PSS + kk + tg];
            a[1] = Ps[(wrow + gq + 8) * PSS + kk + tg];
            a[2] = Ps[(wrow + gq) * PSS + kk + tg + 4];
            a[3] = Ps[(wrow + gq + 8) * PSS + kk + tg + 4];
            #pragma unroll
            for (int nt = 0; nt < 8; nt++) {
                uint32_t b[2];
                b[0] = Vs[(sb * 64 + kk + tg) * VSS + nt * 8 + gq];
                b[1] = Vs[(sb * 64 + kk + tg + 4) * VSS + nt * 8 + gq];
                mma_tf32(o[nt], a, b, o[nt]);
            }
        }
        __syncwarp();   // Ps rows are warp-private; order WAR for next sb
    }

    // ---- finalize: write tf32 bit patterns (consumed by proj_mma cp.async) ----
    const float inv0 = 1.0f / l0;
    const float inv1 = 1.0f / l1;
    #pragma unroll
    for (int nt = 0; nt < 8; nt++) {
        const int col = nt * 8 + 2 * tg;
        float2 v0 = make_float2(__uint_as_float(f2tf(o[nt][0] * inv0)),
                                __uint_as_float(f2tf(o[nt][1] * inv0)));
        *(float2*)&g_o[base + (size_t)row0 * Dh + col] = v0;
        float2 v1 = make_float2(__uint_as_float(f2tf(o[nt][2] * inv1)),
                                __uint_as_float(f2tf(o[nt][3] * inv1)));
        *(float2*)&g_o[base + (size_t)row1 * Dh + col] = v1;
    }
}

// ---------------------------------------------------------------------------
extern "C" void kernel_launch(void* const* d_in, const int* in_sizes, int n_in,
                              void* d_out, int out_size)
{
    const float* x  = (const float*)d_in[0];
    const float* Wq = (const float*)d_in[1];
    const float* Wk = (const float*)d_in[2];
    const float* Wv = (const float*)d_in[3];
    const float* Wp = (const float*)d_in[4];
    const float* bp = (const float*)d_in[5];
    float* out = (float*)d_out;

    (void)in_sizes; (void)n_in; (void)out_size;

    cudaFuncSetAttribute(qkv_mma,
                         cudaFuncAttributeMaxDynamicSharedMemorySize, GEMM_SMEM_BYTES);
    cudaFuncSetAttribute(proj_mma,
                         cudaFuncAttributeMaxDynamicSharedMemorySize, GEMM_SMEM_BYTES);
    cudaFuncSetAttribute(attn4_kernel,
                         cudaFuncAttributeMaxDynamicSharedMemorySize, ATT4_SMEM_BYTES);

    cvt_x_kernel<<<(MTOT * Cdim / 4) / 256, 256>>>(x);
    cvt_w_kernel<<<(4 * Cdim * 384) / 256, 256>>>(Wq, Wk, Wv, Wp);
    qkv_mma<<<dim3(9, 128), 256, GEMM_SMEM_BYTES>>>();
    attn4_kernel<<<dim3(Bsz * Hn), 512, ATT4_SMEM_BYTES>>>();
    proj_mma<<<dim3(3, 128), 256, GEMM_SMEM_BYTES>>>(bp, out);
}

// round 8
// speedup vs baseline: 3.7053x; 1.0001x over previous
#include <cuda_runtime.h>
#include <math.h>
#include <stdint.h>

#define Bsz  64
#define Tlen 256
#define Cdim 384
#define Hn   6
#define Dh   64
#define MTOT (Bsz*Tlen)
#define QKV_ELEMS (Bsz*Hn*Tlen*Dh)   // 6291456

__device__ float g_q[QKV_ELEMS];
__device__ float g_k[QKV_ELEMS];
__device__ float g_v[QKV_ELEMS];
__device__ float g_o[QKV_ELEMS];          // tf32 bit patterns after attn

__device__ uint32_t g_xt[MTOT * Cdim];    // X as tf32
__device__ uint32_t g_wb[3 * Cdim * 384]; // [mat][k][n], n = h*64+d, tf32
__device__ uint32_t g_wpt[Cdim * Cdim];   // [k][n] = Wp[n][k], tf32

// ---------------------------------------------------------------------------
// helpers
// ---------------------------------------------------------------------------
__device__ __forceinline__ uint32_t f2tf(float f) {
    uint32_t r;
    asm("cvt.rna.tf32.f32 %0, %1;" : "=r"(r) : "f"(f));
    return r;
}

__device__ __forceinline__ void mma_tf32(float d[4], const uint32_t a[4],
                                         const uint32_t b[2], const float c[4]) {
    asm volatile(
        "mma.sync.aligned.m16n8k8.row.col.f32.tf32.tf32.f32 "
        "{%0,%1,%2,%3}, {%4,%5,%6,%7}, {%8,%9}, {%10,%11,%12,%13};"
        : "=f"(d[0]), "=f"(d[1]), "=f"(d[2]), "=f"(d[3])
        : "r"(a[0]), "r"(a[1]), "r"(a[2]), "r"(a[3]),
          "r"(b[0]), "r"(b[1]),
          "f"(c[0]), "f"(c[1]), "f"(c[2]), "f"(c[3]));
}

__device__ __forceinline__ void cp16(void* dst, const void* src) {
    uint32_t s = (uint32_t)__cvta_generic_to_shared(dst);
    asm volatile("cp.async.ca.shared.global [%0], [%1], 16;" :: "r"(s), "l"(src));
}
#define CP_COMMIT() asm volatile("cp.async.commit_group;")
#define CP_WAIT1()  asm volatile("cp.async.wait_group 1;")
#define CP_WAIT0()  asm volatile("cp.async.wait_group 0;")

// ---------------------------------------------------------------------------
// Prologue: convert inputs/weights to tf32 once.
// ---------------------------------------------------------------------------
__global__ __launch_bounds__(256) void cvt_x_kernel(const float* __restrict__ X)
{
    int i = blockIdx.x * 256 + threadIdx.x;       // float4 index
    float4 v = ((const float4*)X)[i];
    uint4 u = make_uint4(f2tf(v.x), f2tf(v.y), f2tf(v.z), f2tf(v.w));
    ((uint4*)g_xt)[i] = u;
}

__global__ __launch_bounds__(256) void cvt_w_kernel(
    const float* __restrict__ Wq, const float* __restrict__ Wk,
    const float* __restrict__ Wv, const float* __restrict__ Wp)
{
    int i = blockIdx.x * 256 + threadIdx.x;
    const int NW = 3 * Cdim * 384;
    if (i < NW) {
        int mat = i / (Cdim * 384);
        int rem = i - mat * (Cdim * 384);
        int k = rem / 384, n = rem - (rem / 384) * 384;
        const float* W = (mat == 0) ? Wq : (mat == 1) ? Wk : Wv;
        int h = n >> 6, d = n & 63;
        g_wb[i] = f2tf(W[((size_t)h * Cdim + k) * Dh + d]);
    } else {
        int j = i - NW;                          // [0, 147456)
        int k = j / 384, n = j - k * 384;
        g_wpt[j] = f2tf(Wp[(size_t)n * Cdim + k]);
    }
}

// ---------------------------------------------------------------------------
// QKV projection: cp.async double-buffered tf32 MMA (round-5, known good).
// ---------------------------------------------------------------------------
#define ASTR 36
#define BSTR 136
#define A_WORDS (128 * ASTR)         // 4608
#define B_WORDS (32 * BSTR)          // 4352
#define GEMM_SMEM_BYTES ((2 * A_WORDS + 2 * B_WORDS) * 4)  // 71680

__global__ __launch_bounds__(256, 2) void qkv_mma(void)
{
    extern __shared__ uint32_t dynsm[];
    uint32_t* Asm = dynsm;
    uint32_t* Bsm = dynsm + 2 * A_WORDS;

    const int tid  = threadIdx.x;
    const int lane = tid & 31;
    const int warp = tid >> 5;
    const int gq   = lane >> 2;
    const int tg   = lane & 3;
    const int warpM = (warp >> 2) * 64;
    const int warpN = (warp & 3) * 32;

    const int nbase = blockIdx.x * 128;
    const int mat   = nbase / 384;
    const int nloc  = nbase - mat * 384;
    float* __restrict__ O = (mat == 0) ? g_q : (mat == 1) ? g_k : g_v;
    const int blockM = blockIdx.y * 128;

    const int arow = tid >> 3;            // 0..31
    const int akf  = (tid & 7) * 4;       // 0..28
    const int bk   = tid >> 5;            // 0..7
    const int bnf  = (tid & 31) * 4;      // 0..124

    const uint32_t* __restrict__ wbase = g_wb + (size_t)mat * Cdim * 384 + nloc;

    auto stage = [&](int kt, int buf) {
        uint32_t* A = Asm + buf * A_WORDS;
        uint32_t* B = Bsm + buf * B_WORDS;
        #pragma unroll
        for (int p = 0; p < 4; p++) {
            int m = arow + 32 * p;
            cp16(&A[m * ASTR + akf], &g_xt[(size_t)(blockM + m) * Cdim + kt + akf]);
        }
        #pragma unroll
        for (int p = 0; p < 4; p++) {
            int k = bk + 8 * p;
            cp16(&B[k * BSTR + bnf], &wbase[(size_t)(kt + k) * 384 + bnf]);
        }
    };

    float acc[4][4][4];
    #pragma unroll
    for (int mt = 0; mt < 4; mt++)
        #pragma unroll
        for (int nt = 0; nt < 4; nt++)
            #pragma unroll
            for (int i = 0; i < 4; i++) acc[mt][nt][i] = 0.f;

    stage(0, 0);
    CP_COMMIT();

    const int NK = Cdim / 32;   // 12
    for (int it = 0; it < NK; it++) {
        if (it + 1 < NK) { stage(32 * (it + 1), (it + 1) & 1); CP_COMMIT(); CP_WAIT1(); }
        else            { CP_WAIT0(); }
        __syncthreads();

        const uint32_t* As = Asm + (it & 1) * A_WORDS;
        const uint32_t* Bs = Bsm + (it & 1) * B_WORDS;

        #pragma unroll
        for (int ks = 0; ks < 4; ks++) {
            const int k0 = ks * 8;
            uint32_t a[4][4];
            #pragma unroll
            for (int mt = 0; mt < 4; mt++) {
                int r0 = warpM + mt * 16 + gq;
                a[mt][0] = As[r0 * ASTR + k0 + tg];
                a[mt][1] = As[(r0 + 8) * ASTR + k0 + tg];
                a[mt][2] = As[r0 * ASTR + k0 + tg + 4];
                a[mt][3] = As[(r0 + 8) * ASTR + k0 + tg + 4];
            }
            uint32_t b[4][2];
            #pragma unroll
            for (int nt = 0; nt < 4; nt++) {
                int c0 = warpN + nt * 8 + gq;
                b[nt][0] = Bs[(k0 + tg) * BSTR + c0];
                b[nt][1] = Bs[(k0 + tg + 4) * BSTR + c0];
            }
            #pragma unroll
            for (int mt = 0; mt < 4; mt++)
                #pragma unroll
                for (int nt = 0; nt < 4; nt++)
                    mma_tf32(acc[mt][nt], a[mt], b[nt], acc[mt][nt]);
        }
        __syncthreads();
    }

    #pragma unroll
    for (int mt = 0; mt < 4; mt++) {
        #pragma unroll
        for (int nt = 0; nt < 4; nt++) {
            int cloc = nloc + warpN + nt * 8 + 2 * tg;
            int h = cloc >> 6, d = cloc & 63;
            int r = blockM + warpM + mt * 16 + gq;
            int bb = r >> 8, t = r & 255;
            float2 v0 = make_float2(acc[mt][nt][0], acc[mt][nt][1]);
            *(float2*)&O[(((size_t)bb * Hn + h) * Tlen + t) * Dh + d] = v0;
            float2 v1 = make_float2(acc[mt][nt][2], acc[mt][nt][3]);
            *(float2*)&O[(((size_t)bb * Hn + h) * Tlen + (t + 8)) * Dh + d] = v1;
        }
    }
}

// ---------------------------------------------------------------------------
// Output projection: cp.async double-buffered tf32 MMA (round-5, known good).
// ---------------------------------------------------------------------------
__global__ __launch_bounds__(256, 2) void proj_mma(
    const float* __restrict__ bp,
    float* __restrict__ out)
{
    extern __shared__ uint32_t dynsm[];
    uint32_t* Asm = dynsm;
    uint32_t* Bsm = dynsm + 2 * A_WORDS;

    const int tid  = threadIdx.x;
    const int lane = tid & 31;
    const int warp = tid >> 5;
    const int gq   = lane >> 2;
    const int tg   = lane & 3;
    const int warpM = (warp >> 2) * 64;
    const int warpN = (warp & 3) * 32;

    const int blockN = blockIdx.x * 128;
    const int blockM = blockIdx.y * 128;

    const int arow = tid >> 3;
    const int akf  = (tid & 7) * 4;
    const int bk   = tid >> 5;
    const int bnf  = (tid & 31) * 4;

    auto stage = [&](int kt, int buf) {
        uint32_t* A = Asm + buf * A_WORDS;
        uint32_t* B = Bsm + buf * B_WORDS;
        #pragma unroll
        for (int p = 0; p < 4; p++) {
            int m = arow + 32 * p;
            int mg = blockM + m;
            int kg = kt + akf;
            size_t addr = (((size_t)(mg >> 8)) * Hn + (kg >> 6)) * (Tlen * Dh)
                        + (size_t)(mg & 255) * Dh + (kg & 63);
            cp16(&A[m * ASTR + akf], &g_o[addr]);
        }
        #pragma unroll
        for (int p = 0; p < 4; p++) {
            int k = bk + 8 * p;
            cp16(&B[k * BSTR + bnf], &g_wpt[(size_t)(kt + k) * 384 + blockN + bnf]);
        }
    };

    float acc[4][4][4];
    #pragma unroll
    for (int mt = 0; mt < 4; mt++)
        #pragma unroll
        for (int nt = 0; nt < 4; nt++)
            #pragma unroll
            for (int i = 0; i < 4; i++) acc[mt][nt][i] = 0.f;

    stage(0, 0);
    CP_COMMIT();

    const int NK = Cdim / 32;
    for (int it = 0; it < NK; it++) {
        if (it + 1 < NK) { stage(32 * (it + 1), (it + 1) & 1); CP_COMMIT(); CP_WAIT1(); }
        else            { CP_WAIT0(); }
        __syncthreads();

        const uint32_t* As = Asm + (it & 1) * A_WORDS;
        const uint32_t* Bs = Bsm + (it & 1) * B_WORDS;

        #pragma unroll
        for (int ks = 0; ks < 4; ks++) {
            const int k0 = ks * 8;
            uint32_t a[4][4];
            #pragma unroll
            for (int mt = 0; mt < 4; mt++) {
                int r0 = warpM + mt * 16 + gq;
                a[mt][0] = As[r0 * ASTR + k0 + tg];
                a[mt][1] = As[(r0 + 8) * ASTR + k0 + tg];
                a[mt][2] = As[r0 * ASTR + k0 + tg + 4];
                a[mt][3] = As[(r0 + 8) * ASTR + k0 + tg + 4];
            }
            uint32_t b[4][2];
            #pragma unroll
            for (int nt = 0; nt < 4; nt++) {
                int c0 = warpN + nt * 8 + gq;
                b[nt][0] = Bs[(k0 + tg) * BSTR + c0];
                b[nt][1] = Bs[(k0 + tg + 4) * BSTR + c0];
            }
            #pragma unroll
            for (int mt = 0; mt < 4; mt++)
                #pragma unroll
                for (int nt = 0; nt < 4; nt++)
                    mma_tf32(acc[mt][nt], a[mt], b[nt], acc[mt][nt]);
        }
        __syncthreads();
    }

    #pragma unroll
    for (int mt = 0; mt < 4; mt++) {
        #pragma unroll
        for (int nt = 0; nt < 4; nt++) {
            int n = blockN + warpN + nt * 8 + 2 * tg;
            float b0 = bp[n], b1 = bp[n + 1];
            int r = blockM + warpM + mt * 16 + gq;
            float2 v0 = make_float2(acc[mt][nt][0] + b0, acc[mt][nt][1] + b1);
            *(float2*)&out[(size_t)r * Cdim + n] = v0;
            float2 v1 = make_float2(acc[mt][nt][2] + b0, acc[mt][nt][3] + b1);
            *(float2*)&out[(size_t)(r + 8) * Cdim + n] = v1;
        }
    }
}

// ---------------------------------------------------------------------------
// attn4: 16 warps per CTA, warp w owns rows [16w, 16w+16) of full T=256.
// Q fragments in registers (loaded once from g_q). No Qs buffer, no
// block-level syncs after staging. Causal: warp w runs wrow/64+1 s-blocks.
// ---------------------------------------------------------------------------
#define KTS 264
#define VSS 72
#define PSS 68
#define A4_KT 0
#define A4_VS (A4_KT + 64 * KTS)                // 16896
#define A4_PS (A4_VS + 256 * VSS)               // 35328
#define ATT4_SMEM_WORDS (A4_PS + 256 * PSS)     // 52736
#define ATT4_SMEM_BYTES (ATT4_SMEM_WORDS * 4)   // 210944

__global__ __launch_bounds__(512) void attn4_kernel()
{
    extern __shared__ __align__(16) uint32_t smu[];
    uint32_t* Kt = smu + A4_KT;
    uint32_t* Vs = smu + A4_VS;
    uint32_t* Ps = smu + A4_PS;

    const int bh = blockIdx.x;
    const size_t base = (size_t)bh * (Tlen * Dh);
    const int tid  = threadIdx.x;
    const int lane = tid & 31;
    const int warp = tid >> 5;           // 0..15
    const int gq   = lane >> 2;
    const int tg   = lane & 3;
    const int wrow = warp * 16;

    // --- Stage K transposed: Kt[d][s] ---
    {
        const int s0  = tid & 31;
        const int d4b = tid >> 5;        // 0..15
        #pragma unroll
        for (int it = 0; it < 8; it++) {
            int s  = s0 + 32 * it;
            float4 v = *(const float4*)&g_k[base + (size_t)s * Dh + d4b * 4];
            Kt[(4 * d4b + 0) * KTS + s] = f2tf(v.x);
            Kt[(4 * d4b + 1) * KTS + s] = f2tf(v.y);
            Kt[(4 * d4b + 2) * KTS + s] = f2tf(v.z);
            Kt[(4 * d4b + 3) * KTS + s] = f2tf(v.w);
        }
    }
    // --- Stage V natural: Vs[s][d] ---
    #pragma unroll
    for (int it = 0; it < 8; it++) {
        int idx = tid + 512 * it;        // float4 index, [0,4096)
        int s = idx >> 4, d4 = idx & 15;
        float4 v = *(const float4*)&g_v[base + (size_t)idx * 4];
        uint4 u = make_uint4(f2tf(v.x), f2tf(v.y), f2tf(v.z), f2tf(v.w));
        *(uint4*)&Vs[s * VSS + 4 * d4] = u;
    }

    // --- Q fragments in registers (reused across all s-blocks) ---
    const int row0 = wrow + gq;
    const int row1 = row0 + 8;
    uint32_t qfr[8][4];
    {
        const float* q0 = &g_q[base + (size_t)row0 * Dh];
        const float* q1 = &g_q[base + (size_t)row1 * Dh];
        #pragma unroll
        for (int ks = 0; ks < 8; ks++) {
            const int kk = ks * 8;
            qfr[ks][0] = f2tf(q0[kk + tg]);
            qfr[ks][1] = f2tf(q1[kk + tg]);
            qfr[ks][2] = f2tf(q0[kk + tg + 4]);
            qfr[ks][3] = f2tf(q1[kk + tg + 4]);
        }
    }
    __syncthreads();

    const float scale = 0.125f;

    float m0r = -INFINITY, m1r = -INFINITY;
    float l0 = 0.f, l1 = 0.f;
    float o[8][4];
    #pragma unroll
    for (int nt = 0; nt < 8; nt++)
        #pragma unroll
        for (int c = 0; c < 4; c++) o[nt][c] = 0.f;

    const int nblocks = (wrow >> 6) + 1;       // 1..4, warp-uniform
    for (int sb = 0; sb < nblocks; sb++) {

        // ---- S = Q K^T (16 rows x 64 cols) ----
        float sacc[8][4];
        #pragma unroll
        for (int nt = 0; nt < 8; nt++)
            #pragma unroll
            for (int c = 0; c < 4; c++) sacc[nt][c] = 0.f;

        #pragma unroll
        for (int ks = 0; ks < 8; ks++) {
            const int kk = ks * 8;
            #pragma unroll
            for (int nt = 0; nt < 8; nt++) {
                uint32_t b[2];
                const int cc = sb * 64 + nt * 8 + gq;
                b[0] = Kt[(kk + tg) * KTS + cc];
                b[1] = Kt[(kk + tg + 4) * KTS + cc];
                mma_tf32(sacc[nt], qfr[ks], b, sacc[nt]);
            }
        }

        // ---- mask + online softmax ----
        float bm0 = -INFINITY, bm1 = -INFINITY;
        #pragma unroll
        for (int nt = 0; nt < 8; nt++) {
            const int c0 = sb * 64 + nt * 8 + 2 * tg;
            float v00 = (c0     <= row0) ? sacc[nt][0] * scale : -INFINITY;
            float v01 = (c0 + 1 <= row0) ? sacc[nt][1] * scale : -INFINITY;
            float v10 = (c0     <= row1) ? sacc[nt][2] * scale : -INFINITY;
            float v11 = (c0 + 1 <= row1) ? sacc[nt][3] * scale : -INFINITY;
            sacc[nt][0] = v00; sacc[nt][1] = v01;
            sacc[nt][2] = v10; sacc[nt][3] = v11;
            bm0 = fmaxf(bm0, fmaxf(v00, v01));
            bm1 = fmaxf(bm1, fmaxf(v10, v11));
        }
        bm0 = fmaxf(bm0, __shfl_xor_sync(0xffffffffu, bm0, 1));
        bm0 = fmaxf(bm0, __shfl_xor_sync(0xffffffffu, bm0, 2));
        bm1 = fmaxf(bm1, __shfl_xor_sync(0xffffffffu, bm1, 1));
        bm1 = fmaxf(bm1, __shfl_xor_sync(0xffffffffu, bm1, 2));

        const float mn0 = fmaxf(m0r, bm0);
        const float mn1 = fmaxf(m1r, bm1);
        const float cor0 = __expf(m0r - mn0);
        const float cor1 = __expf(m1r - mn1);
        m0r = mn0; m1r = mn1;

        float rs0 = 0.f, rs1 = 0.f;
        #pragma unroll
        for (int nt = 0; nt < 8; nt++) {
            float p00 = __expf(sacc[nt][0] - mn0);
            float p01 = __expf(sacc[nt][1] - mn0);
            float p10 = __expf(sacc[nt][2] - mn1);
            float p11 = __expf(sacc[nt][3] - mn1);
            rs0 += p00 + p01;
            rs1 += p10 + p11;
            uint2 u0 = make_uint2(f2tf(p00), f2tf(p01));
            *(uint2*)&Ps[(wrow + gq) * PSS + nt * 8 + 2 * tg] = u0;
            uint2 u1 = make_uint2(f2tf(p10), f2tf(p11));
            *(uint2*)&Ps[(wrow + gq + 8) * PSS + nt * 8 + 2 * tg] = u1;
        }
        rs0 += __shfl_xor_sync(0xffffffffu, rs0, 1);
        rs0 += __shfl_xor_sync(0xffffffffu, rs0, 2);
        rs1 += __shfl_xor_sync(0xffffffffu, rs1, 1);
        rs1 += __shfl_xor_sync(0xffffffffu, rs1, 2);
        l0 = l0 * cor0 + rs0;
        l1 = l1 * cor1 + rs1;

        #pragma unroll
        for (int nt = 0; nt < 8; nt++) {
            o[nt][0] *= cor0; o[nt][1] *= cor0;
            o[nt][2] *= cor1; o[nt][3] *= cor1;
        }
        __syncwarp();

        // ---- O += P V ----
        #pragma unroll
        for (int ks = 0; ks < 8; ks++) {
            const int kk = ks * 8;
            uint32_t a[4];
            a[0] = Ps[(wrow + gq) * PSS + kk + tg];
            a[1] = Ps[(wrow + gq + 8) * PSS + kk + tg];
            a[2] = Ps[(wrow + gq) * PSS + kk + tg + 4];
            a[3] = Ps[(wrow + gq + 8) * PSS + kk + tg + 4];
            #pragma unroll
            for (int nt = 0; nt < 8; nt++) {
                uint32_t b[2];
                b[0] = Vs[(sb * 64 + kk + tg) * VSS + nt * 8 + gq];
                b[1] = Vs[(sb * 64 + kk + tg + 4) * VSS + nt * 8 + gq];
                mma_tf32(o[nt], a, b, o[nt]);
            }
        }
        __syncwarp();   // Ps rows are warp-private; order WAR for next sb
    }

    // ---- finalize: write tf32 bit patterns (consumed by proj_mma cp.async) ----
    const float inv0 = 1.0f / l0;
    const float inv1 = 1.0f / l1;
    #pragma unroll
    for (int nt = 0; nt < 8; nt++) {
        const int col = nt * 8 + 2 * tg;
        float2 v0 = make_float2(__uint_as_float(f2tf(o[nt][0] * inv0)),
                                __uint_as_float(f2tf(o[nt][1] * inv0)));
        *(float2*)&g_o[base + (size_t)row0 * Dh + col] = v0;
        float2 v1 = make_float2(__uint_as_float(f2tf(o[nt][2] * inv1)),
                                __uint_as_float(f2tf(o[nt][3] * inv1)));
        *(float2*)&g_o[base + (size_t)row1 * Dh + col] = v1;
    }
}

// ---------------------------------------------------------------------------
extern "C" void kernel_launch(void* const* d_in, const int* in_sizes, int n_in,
                              void* d_out, int out_size)
{
    const float* x  = (const float*)d_in[0];
    const float* Wq = (const float*)d_in[1];
    const float* Wk = (const float*)d_in[2];
    const float* Wv = (const float*)d_in[3];
    const float* Wp = (const float*)d_in[4];
    const float* bp = (const float*)d_in[5];
    float* out = (float*)d_out;

    (void)in_sizes; (void)n_in; (void)out_size;

    cudaFuncSetAttribute(qkv_mma,
                         cudaFuncAttributeMaxDynamicSharedMemorySize, GEMM_SMEM_BYTES);
    cudaFuncSetAttribute(proj_mma,
                         cudaFuncAttributeMaxDynamicSharedMemorySize, GEMM_SMEM_BYTES);
    cudaFuncSetAttribute(attn4_kernel,
                         cudaFuncAttributeMaxDynamicSharedMemorySize, ATT4_SMEM_BYTES);

    cvt_x_kernel<<<(MTOT * Cdim / 4) / 256, 256>>>(x);
    cvt_w_kernel<<<(4 * Cdim * 384) / 256, 256>>>(Wq, Wk, Wv, Wp);
    qkv_mma<<<dim3(9, 128), 256, GEMM_SMEM_BYTES>>>();
    attn4_kernel<<<dim3(Bsz * Hn), 512, ATT4_SMEM_BYTES>>>();
    proj_mma<<<dim3(3, 128), 256, GEMM_SMEM_BYTES>>>(bp, out);
}